// round 1
// baseline (speedup 1.0000x reference)
#include <cuda_runtime.h>
#include <math.h>

#define BATCH 128
#define NOUT  10
#define NIN   1152
#define DOUT  16
#define DIN   8
#define H1    512
#define H2    1024
#define PIX   784
#define BN    (BATCH*NOUT)   // 1280

// ---- scratch (device globals; no allocations allowed) ----
__device__ float g_hat[(size_t)BATCH*NOUT*NIN*DOUT];  // 94.4 MB
__device__ float g_bcoef[(size_t)BATCH*NOUT*NIN];
__device__ float g_c[(size_t)BATCH*NOUT*NIN];
__device__ float g_outcaps[BN*DOUT];
__device__ float g_h1[(size_t)BN*H1];
__device__ float g_h2[(size_t)BN*H2];
__device__ float g_recon[(size_t)BN*PIX];
__device__ float g_rscore[BN];
__device__ float g_r[BN];

// ---- hat[b,n,k,o] = sum_i weight[n,k,o,i] * incaps[b,k,i] ----
__global__ void k_hat(const float* __restrict__ incaps,
                      const float* __restrict__ weight) {
    int tid = blockIdx.x * blockDim.x + threadIdx.x;   // exact grid
    int o = tid & 15;
    int k = (tid >> 4) % NIN;
    int n = ((tid >> 4) / NIN) % NOUT;
    int b = tid / (16 * NIN * NOUT);
    const float4* w = (const float4*)(weight + ((size_t)(n*NIN + k)*DOUT + o)*DIN);
    const float4* x = (const float4*)(incaps + ((size_t)b*NIN + k)*DIN);
    float4 w0 = w[0], w1 = w[1], x0 = x[0], x1 = x[1];
    float s = w0.x*x0.x + w0.y*x0.y + w0.z*x0.z + w0.w*x0.w
            + w1.x*x1.x + w1.y*x1.y + w1.z*x1.z + w1.w*x1.w;
    g_hat[tid] = s;
}

// ---- per (b,n): S=sum_k rc*hat ; outcaps=squash(S) ; bcoef[k]=outcaps.hat[k] ----
__global__ void k_routing(int use_rc, int do_b, float* __restrict__ out_vec) {
    int bn  = blockIdx.x;           // b*NOUT + n
    int tid = threadIdx.x;          // 256 threads
    const float* hat = g_hat + (size_t)bn * NIN * DOUT;
    float rglob = use_rc ? g_r[bn] : 1.0f;

    float acc[16];
#pragma unroll
    for (int o = 0; o < 16; o++) acc[o] = 0.f;

    for (int k = tid; k < NIN; k += 256) {
        float rcv = use_rc ? g_c[(size_t)bn*NIN + k] * rglob : 1.0f;
        const float4* h4 = (const float4*)(hat + (size_t)k * 16);
        float4 a = h4[0], b4 = h4[1], c4 = h4[2], d4 = h4[3];
        acc[0]  += rcv*a.x;  acc[1]  += rcv*a.y;  acc[2]  += rcv*a.z;  acc[3]  += rcv*a.w;
        acc[4]  += rcv*b4.x; acc[5]  += rcv*b4.y; acc[6]  += rcv*b4.z; acc[7]  += rcv*b4.w;
        acc[8]  += rcv*c4.x; acc[9]  += rcv*c4.y; acc[10] += rcv*c4.z; acc[11] += rcv*c4.w;
        acc[12] += rcv*d4.x; acc[13] += rcv*d4.y; acc[14] += rcv*d4.z; acc[15] += rcv*d4.w;
    }

    __shared__ float red[256 * 16];
#pragma unroll
    for (int o = 0; o < 16; o++) red[tid*16 + o] = acc[o];
    __syncthreads();
    for (int s = 128; s > 0; s >>= 1) {
        if (tid < s) {
#pragma unroll
            for (int o = 0; o < 16; o++) red[tid*16 + o] += red[(tid+s)*16 + o];
        }
        __syncthreads();
    }

    __shared__ float oc[16];
    if (tid == 0) {
        float n2 = 0.f;
#pragma unroll
        for (int o = 0; o < 16; o++) { float v = red[o]; n2 += v*v; }
        float nrm   = sqrtf(n2);
        float scale = n2 / (1.f + n2) / (nrm + 1e-8f);
        float* dst = out_vec ? out_vec : g_outcaps;
#pragma unroll
        for (int o = 0; o < 16; o++) {
            float v = scale * red[o];
            oc[o] = v;
            dst[(size_t)bn*16 + o] = v;
        }
    }
    __syncthreads();
    if (!do_b) return;

    for (int k = tid; k < NIN; k += 256) {
        const float4* h4 = (const float4*)(hat + (size_t)k * 16);
        float4 a = h4[0], b4 = h4[1], c4 = h4[2], d4 = h4[3];
        float s = a.x*oc[0]  + a.y*oc[1]  + a.z*oc[2]  + a.w*oc[3]
                + b4.x*oc[4] + b4.y*oc[5] + b4.z*oc[6] + b4.w*oc[7]
                + c4.x*oc[8] + c4.y*oc[9] + c4.z*oc[10]+ c4.w*oc[11]
                + d4.x*oc[12]+ d4.y*oc[13]+ d4.z*oc[14]+ d4.w*oc[15];
        g_bcoef[(size_t)bn*NIN + k] = s;
    }
}

// ---- c = scale_coef(bcoef) over axis n (first 9), bg slot -> 0.5 ----
__global__ void k_scale_c() {
    int idx = blockIdx.x * blockDim.x + threadIdx.x;    // over B*NIN
    if (idx >= BATCH * NIN) return;
    int b = idx / NIN, k = idx % NIN;
    float v[9];
    float mn = 1e30f, mx = -1e30f;
#pragma unroll
    for (int n = 0; n < 9; n++) {
        float t = g_bcoef[((size_t)b*NOUT + n)*NIN + k];
        v[n] = t; mn = fminf(mn, t); mx = fmaxf(mx, t);
    }
    float denom = fmaxf(mx - mn, 1e-6f);
#pragma unroll
    for (int n = 0; n < 9; n++)
        g_c[((size_t)b*NOUT + n)*NIN + k] = fmaxf((v[n]-mn)/denom, 0.5f);
    g_c[((size_t)b*NOUT + 9)*NIN + k] = 0.5f;
}

// ---- layer1: only 16 inputs are nonzero (slot m) ----
__global__ void k_h1(const float* __restrict__ W1, const float* __restrict__ b1) {
    int r = blockIdx.x;                       // b*NOUT + m
    int j = blockIdx.y * blockDim.x + threadIdx.x;   // 0..511
    int m = r % NOUT;
    __shared__ float oc[16];
    if (threadIdx.x < 16) oc[threadIdx.x] = g_outcaps[(size_t)r*16 + threadIdx.x];
    __syncthreads();
    float s = b1[j];
#pragma unroll
    for (int d = 0; d < 16; d++)
        s += oc[d] * W1[(size_t)(m*16 + d)*H1 + j];
    g_h1[(size_t)r*H1 + j] = fmaxf(s, 0.f);
}

// ---- tiled fp32 GEMM: C = epi(A[M,Kd] @ B[Kd,N] + bias) ----
// EPI: 1=relu, 2=sigmoid
template <int EPI>
__global__ void k_gemm(const float* __restrict__ A, const float* __restrict__ B,
                       const float* __restrict__ bias, float* __restrict__ C,
                       int M, int N, int Kd) {
    __shared__ float As[16][64];
    __shared__ float Bs[16][64];
    int tid  = threadIdx.x;          // 256
    int row0 = blockIdx.y * 64, col0 = blockIdx.x * 64;
    int tx = tid & 15, ty = tid >> 4;
    int arow = tid >> 2, akc = (tid & 3) * 4;
    int bkr  = tid >> 4, bc  = (tid & 15) * 4;
    float acc[4][4] = {};

    for (int k0 = 0; k0 < Kd; k0 += 16) {
        float4 av = *(const float4*)(A + (size_t)(row0 + arow)*Kd + k0 + akc);
        As[akc+0][arow] = av.x; As[akc+1][arow] = av.y;
        As[akc+2][arow] = av.z; As[akc+3][arow] = av.w;
        if (col0 + bc + 3 < N) {
            *(float4*)&Bs[bkr][bc] = *(const float4*)(B + (size_t)(k0 + bkr)*N + col0 + bc);
        } else {
#pragma unroll
            for (int j = 0; j < 4; j++)
                Bs[bkr][bc+j] = (col0 + bc + j < N) ? B[(size_t)(k0 + bkr)*N + col0 + bc + j] : 0.f;
        }
        __syncthreads();
#pragma unroll
        for (int kk = 0; kk < 16; kk++) {
            float4 ra = *(const float4*)&As[kk][ty*4];
            float4 rb = *(const float4*)&Bs[kk][tx*4];
            float a_[4] = {ra.x, ra.y, ra.z, ra.w};
            float b_[4] = {rb.x, rb.y, rb.z, rb.w};
#pragma unroll
            for (int i = 0; i < 4; i++)
#pragma unroll
                for (int j = 0; j < 4; j++) acc[i][j] += a_[i] * b_[j];
        }
        __syncthreads();
    }

#pragma unroll
    for (int i = 0; i < 4; i++) {
        int row = row0 + ty*4 + i;
#pragma unroll
        for (int j = 0; j < 4; j++) {
            int col = col0 + tx*4 + j;
            if (col < N) {
                float v = acc[i][j] + bias[col];
                if (EPI == 1)      v = fmaxf(v, 0.f);
                else if (EPI == 2) v = 1.f / (1.f + __expf(-v));
                C[(size_t)row*N + col] = v;
            }
        }
    }
}

// ---- rscore[b,m] = -sum_p (x[b,p] - recon[b,m,p])^2 ----
__global__ void k_rscore(const float* __restrict__ x) {
    int r = blockIdx.x;               // b*NOUT + m
    int b = r / NOUT;
    int tid = threadIdx.x;
    float s = 0.f;
    for (int p = tid; p < PIX; p += 256) {
        float d = x[(size_t)b*PIX + p] - g_recon[(size_t)r*PIX + p];
        s += d * d;
    }
    __shared__ float red[256];
    red[tid] = s; __syncthreads();
    for (int st = 128; st > 0; st >>= 1) {
        if (tid < st) red[tid] += red[tid + st];
        __syncthreads();
    }
    if (tid == 0) g_rscore[r] = -red[0];
}

// ---- r = scale_coef(rscore) over m ----
__global__ void k_scale_r() {
    int b = threadIdx.x;
    if (b >= BATCH) return;
    float v[9];
    float mn = 1e30f, mx = -1e30f;
#pragma unroll
    for (int m = 0; m < 9; m++) {
        float t = g_rscore[b*NOUT + m];
        v[m] = t; mn = fminf(mn, t); mx = fmaxf(mx, t);
    }
    float denom = fmaxf(mx - mn, 1e-6f);
#pragma unroll
    for (int m = 0; m < 9; m++)
        g_r[b*NOUT + m] = fmaxf((v[m]-mn)/denom, 0.5f);
    g_r[b*NOUT + 9] = 0.5f;
}

extern "C" void kernel_launch(void* const* d_in, const int* in_sizes, int n_in,
                              void* d_out, int out_size) {
    const float* incaps = (const float*)d_in[0];
    const float* x      = (const float*)d_in[1];
    const float* weight = (const float*)d_in[2];
    const float* W1     = (const float*)d_in[3];
    const float* b1     = (const float*)d_in[4];
    const float* W2     = (const float*)d_in[5];
    const float* b2     = (const float*)d_in[6];
    const float* W3     = (const float*)d_in[7];
    const float* b3     = (const float*)d_in[8];
    float* out = (float*)d_out;

    float *p_h1, *p_h2, *p_recon;
    cudaGetSymbolAddress((void**)&p_h1,    g_h1);
    cudaGetSymbolAddress((void**)&p_h2,    g_h2);
    cudaGetSymbolAddress((void**)&p_recon, g_recon);

    int tot = BATCH * NOUT * NIN * DOUT;
    k_hat<<<tot/256, 256>>>(incaps, weight);

    for (int it = 0; it < 2; it++) {
        k_routing<<<BN, 256>>>(it > 0 ? 1 : 0, 1, nullptr);
        k_scale_c<<<(BATCH*NIN + 255)/256, 256>>>();
        k_h1<<<dim3(BN, 2), 256>>>(W1, b1);
        k_gemm<1><<<dim3(H2/64, BN/64), 256>>>(p_h1, W2, b2, p_h2, BN, H2, H1);
        k_gemm<2><<<dim3((PIX+63)/64, BN/64), 256>>>(p_h2, W3, b3, p_recon, BN, PIX, H2);
        k_rscore<<<BN, 256>>>(x);
        k_scale_r<<<1, 128>>>();
    }
    k_routing<<<BN, 256>>>(1, 0, out);
}

// round 2
// speedup vs baseline: 1.6051x; 1.6051x over previous
#include <cuda_runtime.h>
#include <math.h>

#define BATCH 128
#define NOUT  10
#define NIN   1152
#define DOUT  16
#define DIN   8
#define H1    512
#define H2    1024
#define PIX   784
#define BN    (BATCH*NOUT)   // 1280

// ---- scratch (device globals; no allocations allowed) ----
__device__ float g_hat[(size_t)BATCH*NOUT*NIN*DOUT];  // 94.4 MB
__device__ float g_bcoef[(size_t)BATCH*NOUT*NIN];
__device__ float g_c[(size_t)BATCH*NOUT*NIN];
__device__ float g_outcaps[BN*DOUT];
__device__ float g_h1[(size_t)BN*H1];
__device__ float g_h2[(size_t)BN*H2];
__device__ float g_recon[(size_t)BN*PIX];
__device__ float g_rscore[BN];
__device__ float g_r[BN];

// ---- hat[b,n,k,o] = sum_i weight[n,k,o,i] * incaps[b,k,i] ----
__global__ void k_hat(const float* __restrict__ incaps,
                      const float* __restrict__ weight) {
    int tid = blockIdx.x * blockDim.x + threadIdx.x;   // exact grid
    int o = tid & 15;
    int k = (tid >> 4) % NIN;
    int n = ((tid >> 4) / NIN) % NOUT;
    int b = tid / (16 * NIN * NOUT);
    const float4* w = (const float4*)(weight + ((size_t)(n*NIN + k)*DOUT + o)*DIN);
    const float4* x = (const float4*)(incaps + ((size_t)b*NIN + k)*DIN);
    float4 w0 = w[0], w1 = w[1], x0 = x[0], x1 = x[1];
    float s = w0.x*x0.x + w0.y*x0.y + w0.z*x0.z + w0.w*x0.w
            + w1.x*x1.x + w1.y*x1.y + w1.z*x1.z + w1.w*x1.w;
    g_hat[tid] = s;
}

// ---- per (b,n): S=sum_k rc*hat ; outcaps=squash(S) ; bcoef[k]=outcaps.hat[k] ----
__global__ void k_routing(int use_rc, int do_b, float* __restrict__ out_vec) {
    int bn  = blockIdx.x;           // b*NOUT + n
    int tid = threadIdx.x;          // 256 threads
    const float* hat = g_hat + (size_t)bn * NIN * DOUT;
    float rglob = use_rc ? g_r[bn] : 1.0f;

    float acc[16];
#pragma unroll
    for (int o = 0; o < 16; o++) acc[o] = 0.f;

    for (int k = tid; k < NIN; k += 256) {
        float rcv = use_rc ? g_c[(size_t)bn*NIN + k] * rglob : 1.0f;
        const float4* h4 = (const float4*)(hat + (size_t)k * 16);
        float4 a = h4[0], b4 = h4[1], c4 = h4[2], d4 = h4[3];
        acc[0]  += rcv*a.x;  acc[1]  += rcv*a.y;  acc[2]  += rcv*a.z;  acc[3]  += rcv*a.w;
        acc[4]  += rcv*b4.x; acc[5]  += rcv*b4.y; acc[6]  += rcv*b4.z; acc[7]  += rcv*b4.w;
        acc[8]  += rcv*c4.x; acc[9]  += rcv*c4.y; acc[10] += rcv*c4.z; acc[11] += rcv*c4.w;
        acc[12] += rcv*d4.x; acc[13] += rcv*d4.y; acc[14] += rcv*d4.z; acc[15] += rcv*d4.w;
    }

    __shared__ float red[256 * 16];
#pragma unroll
    for (int o = 0; o < 16; o++) red[tid*16 + o] = acc[o];
    __syncthreads();
    for (int s = 128; s > 0; s >>= 1) {
        if (tid < s) {
#pragma unroll
            for (int o = 0; o < 16; o++) red[tid*16 + o] += red[(tid+s)*16 + o];
        }
        __syncthreads();
    }

    __shared__ float oc[16];
    if (tid == 0) {
        float n2 = 0.f;
#pragma unroll
        for (int o = 0; o < 16; o++) { float v = red[o]; n2 += v*v; }
        float nrm   = sqrtf(n2);
        float scale = n2 / (1.f + n2) / (nrm + 1e-8f);
        float* dst = out_vec ? out_vec : g_outcaps;
#pragma unroll
        for (int o = 0; o < 16; o++) {
            float v = scale * red[o];
            oc[o] = v;
            dst[(size_t)bn*16 + o] = v;
        }
    }
    __syncthreads();
    if (!do_b) return;

    for (int k = tid; k < NIN; k += 256) {
        const float4* h4 = (const float4*)(hat + (size_t)k * 16);
        float4 a = h4[0], b4 = h4[1], c4 = h4[2], d4 = h4[3];
        float s = a.x*oc[0]  + a.y*oc[1]  + a.z*oc[2]  + a.w*oc[3]
                + b4.x*oc[4] + b4.y*oc[5] + b4.z*oc[6] + b4.w*oc[7]
                + c4.x*oc[8] + c4.y*oc[9] + c4.z*oc[10]+ c4.w*oc[11]
                + d4.x*oc[12]+ d4.y*oc[13]+ d4.z*oc[14]+ d4.w*oc[15];
        g_bcoef[(size_t)bn*NIN + k] = s;
    }
}

// ---- c = scale_coef(bcoef) over axis n (first 9), bg slot -> 0.5 ----
__global__ void k_scale_c() {
    int idx = blockIdx.x * blockDim.x + threadIdx.x;    // over B*NIN
    if (idx >= BATCH * NIN) return;
    int b = idx / NIN, k = idx % NIN;
    float v[9];
    float mn = 1e30f, mx = -1e30f;
#pragma unroll
    for (int n = 0; n < 9; n++) {
        float t = g_bcoef[((size_t)b*NOUT + n)*NIN + k];
        v[n] = t; mn = fminf(mn, t); mx = fmaxf(mx, t);
    }
    float denom = fmaxf(mx - mn, 1e-6f);
#pragma unroll
    for (int n = 0; n < 9; n++)
        g_c[((size_t)b*NOUT + n)*NIN + k] = fmaxf((v[n]-mn)/denom, 0.5f);
    g_c[((size_t)b*NOUT + 9)*NIN + k] = 0.5f;
}

// ---- layer1: only 16 inputs are nonzero (slot m) ----
__global__ void k_h1(const float* __restrict__ W1, const float* __restrict__ b1) {
    int r = blockIdx.x;                       // b*NOUT + m
    int j = blockIdx.y * blockDim.x + threadIdx.x;   // 0..511
    int m = r % NOUT;
    __shared__ float oc[16];
    if (threadIdx.x < 16) oc[threadIdx.x] = g_outcaps[(size_t)r*16 + threadIdx.x];
    __syncthreads();
    float s = b1[j];
#pragma unroll
    for (int d = 0; d < 16; d++)
        s += oc[d] * W1[(size_t)(m*16 + d)*H1 + j];
    g_h1[(size_t)r*H1 + j] = fmaxf(s, 0.f);
}

// ---- SGEMM: C = epi(A[M,Kd] @ B[Kd,N] + bias),  BM=128 BN=64 BK=16,
//      256 threads, 8x4 micro-tile, double-buffered smem.
// EPI: 1=relu, 2=sigmoid. M, Kd multiples of 128/16; N may be ragged.
template <int EPI>
__global__ void __launch_bounds__(256) k_gemm(
        const float* __restrict__ A, const float* __restrict__ B,
        const float* __restrict__ bias, float* __restrict__ C,
        int N, int Kd) {
    __shared__ float As[2][16][128];
    __shared__ float Bs[2][16][64];

    const int tid  = threadIdx.x;
    const int row0 = blockIdx.y * 128;
    const int col0 = blockIdx.x * 64;
    const int tx = tid & 15;        // 0..15  (N dir, 4 cols)
    const int ty = tid >> 4;        // 0..15  (M dir, 8 rows)

    // A slab load mapping: each thread owns one row, 8 consecutive k's
    const int arow = tid >> 1;            // 0..127
    const int akc  = (tid & 1) * 8;       // 0 or 8
    // B slab load mapping: 16 rows x 64 cols, one float4 per thread
    const int bkr = tid >> 4;             // 0..15
    const int bc  = (tid & 15) * 4;       // 0..60

    const float* Ap = A + (size_t)(row0 + arow) * Kd + akc;
    const float* Bp = B + (size_t)bkr * N + col0 + bc;

    float acc[8][4];
#pragma unroll
    for (int i = 0; i < 8; i++)
#pragma unroll
        for (int j = 0; j < 4; j++) acc[i][j] = 0.f;

    const int S = Kd >> 4;

    // prefetch slab 0
    float4 pa0 = *(const float4*)(Ap);
    float4 pa1 = *(const float4*)(Ap + 4);
    float4 pb;
    {
        bool ok = (col0 + bc + 3 < N);
        if (ok) pb = *(const float4*)(Bp);
        else {
            float t[4];
#pragma unroll
            for (int j = 0; j < 4; j++)
                t[j] = (col0 + bc + j < N) ? Bp[j] : 0.f;
            pb = make_float4(t[0], t[1], t[2], t[3]);
        }
    }
    // store slab 0 into buf 0
    As[0][akc+0][arow] = pa0.x; As[0][akc+1][arow] = pa0.y;
    As[0][akc+2][arow] = pa0.z; As[0][akc+3][arow] = pa0.w;
    As[0][akc+4][arow] = pa1.x; As[0][akc+5][arow] = pa1.y;
    As[0][akc+6][arow] = pa1.z; As[0][akc+7][arow] = pa1.w;
    *(float4*)&Bs[0][bkr][bc] = pb;
    __syncthreads();

    for (int s = 0; s < S; s++) {
        const int cur = s & 1;
        const int nxt = s + 1;
        if (nxt < S) {
            const float* Ap2 = Ap + (size_t)nxt * 16;
            pa0 = *(const float4*)(Ap2);
            pa1 = *(const float4*)(Ap2 + 4);
            const float* Bp2 = Bp + (size_t)nxt * 16 * N;
            bool ok = (col0 + bc + 3 < N);
            if (ok) pb = *(const float4*)(Bp2);
            else {
                float t[4];
#pragma unroll
                for (int j = 0; j < 4; j++)
                    t[j] = (col0 + bc + j < N) ? Bp2[j] : 0.f;
                pb = make_float4(t[0], t[1], t[2], t[3]);
            }
        }

#pragma unroll
        for (int kk = 0; kk < 16; kk++) {
            float4 a0 = *(const float4*)&As[cur][kk][ty*8];
            float4 a1 = *(const float4*)&As[cur][kk][ty*8 + 4];
            float4 bv = *(const float4*)&Bs[cur][kk][tx*4];
            float av[8] = {a0.x, a0.y, a0.z, a0.w, a1.x, a1.y, a1.z, a1.w};
            float bb[4] = {bv.x, bv.y, bv.z, bv.w};
#pragma unroll
            for (int i = 0; i < 8; i++)
#pragma unroll
                for (int j = 0; j < 4; j++) acc[i][j] += av[i] * bb[j];
        }

        if (nxt < S) {
            const int nb = nxt & 1;
            As[nb][akc+0][arow] = pa0.x; As[nb][akc+1][arow] = pa0.y;
            As[nb][akc+2][arow] = pa0.z; As[nb][akc+3][arow] = pa0.w;
            As[nb][akc+4][arow] = pa1.x; As[nb][akc+5][arow] = pa1.y;
            As[nb][akc+6][arow] = pa1.z; As[nb][akc+7][arow] = pa1.w;
            *(float4*)&Bs[nb][bkr][bc] = pb;
        }
        __syncthreads();
    }

    // epilogue
    float bv[4];
#pragma unroll
    for (int j = 0; j < 4; j++) {
        int col = col0 + tx*4 + j;
        bv[j] = (col < N) ? bias[col] : 0.f;
    }
#pragma unroll
    for (int i = 0; i < 8; i++) {
        int row = row0 + ty*8 + i;
        float* crow = C + (size_t)row * N;
#pragma unroll
        for (int j = 0; j < 4; j++) {
            int col = col0 + tx*4 + j;
            if (col < N) {
                float v = acc[i][j] + bv[j];
                if (EPI == 1)      v = fmaxf(v, 0.f);
                else if (EPI == 2) v = 1.f / (1.f + __expf(-v));
                crow[col] = v;
            }
        }
    }
}

// ---- rscore[b,m] = -sum_p (x[b,p] - recon[b,m,p])^2 ----
__global__ void k_rscore(const float* __restrict__ x) {
    int r = blockIdx.x;               // b*NOUT + m
    int b = r / NOUT;
    int tid = threadIdx.x;
    float s = 0.f;
    for (int p = tid; p < PIX; p += 256) {
        float d = x[(size_t)b*PIX + p] - g_recon[(size_t)r*PIX + p];
        s += d * d;
    }
    __shared__ float red[256];
    red[tid] = s; __syncthreads();
    for (int st = 128; st > 0; st >>= 1) {
        if (tid < st) red[tid] += red[tid + st];
        __syncthreads();
    }
    if (tid == 0) g_rscore[r] = -red[0];
}

// ---- r = scale_coef(rscore) over m ----
__global__ void k_scale_r() {
    int b = threadIdx.x;
    if (b >= BATCH) return;
    float v[9];
    float mn = 1e30f, mx = -1e30f;
#pragma unroll
    for (int m = 0; m < 9; m++) {
        float t = g_rscore[b*NOUT + m];
        v[m] = t; mn = fminf(mn, t); mx = fmaxf(mx, t);
    }
    float denom = fmaxf(mx - mn, 1e-6f);
#pragma unroll
    for (int m = 0; m < 9; m++)
        g_r[b*NOUT + m] = fmaxf((v[m]-mn)/denom, 0.5f);
    g_r[b*NOUT + 9] = 0.5f;
}

extern "C" void kernel_launch(void* const* d_in, const int* in_sizes, int n_in,
                              void* d_out, int out_size) {
    const float* incaps = (const float*)d_in[0];
    const float* x      = (const float*)d_in[1];
    const float* weight = (const float*)d_in[2];
    const float* W1     = (const float*)d_in[3];
    const float* b1     = (const float*)d_in[4];
    const float* W2     = (const float*)d_in[5];
    const float* b2     = (const float*)d_in[6];
    const float* W3     = (const float*)d_in[7];
    const float* b3     = (const float*)d_in[8];
    float* out = (float*)d_out;

    float *p_h1, *p_h2, *p_recon;
    cudaGetSymbolAddress((void**)&p_h1,    g_h1);
    cudaGetSymbolAddress((void**)&p_h2,    g_h2);
    cudaGetSymbolAddress((void**)&p_recon, g_recon);

    int tot = BATCH * NOUT * NIN * DOUT;
    k_hat<<<tot/256, 256>>>(incaps, weight);

    for (int it = 0; it < 2; it++) {
        k_routing<<<BN, 256>>>(it > 0 ? 1 : 0, 1, nullptr);
        k_scale_c<<<(BATCH*NIN + 255)/256, 256>>>();
        k_h1<<<dim3(BN, 2), 256>>>(W1, b1);
        k_gemm<1><<<dim3(H2/64, BN/128), 256>>>(p_h1, W2, b2, p_h2, H2, H1);
        k_gemm<2><<<dim3((PIX+63)/64, BN/128), 256>>>(p_h2, W3, b3, p_recon, PIX, H2);
        k_rscore<<<BN, 256>>>(x);
        k_scale_r<<<1, 128>>>();
    }
    k_routing<<<BN, 256>>>(1, 0, out);
}

// round 3
// speedup vs baseline: 2.0393x; 1.2705x over previous
#include <cuda_runtime.h>
#include <cuda_bf16.h>
#include <math.h>
#include <stdint.h>

#define BATCH 128
#define NOUT  10
#define NIN   1152
#define DOUT  16
#define DIN   8
#define H1    512
#define H2    1024
#define PIX   784
#define BN    (BATCH*NOUT)   // 1280

// ---- scratch (device globals; no allocations allowed) ----
__device__ float g_hat[(size_t)BATCH*NOUT*NIN*DOUT];  // 94.4 MB
__device__ float g_bcoef[(size_t)BATCH*NOUT*NIN];
__device__ float g_c[(size_t)BATCH*NOUT*NIN];
__device__ float g_outcaps[BN*DOUT];
__device__ float g_recon[(size_t)BN*PIX];
__device__ float g_rscore[BN];
__device__ float g_r[BN];

// hi/lo bf16 split operands
__device__ __nv_bfloat16 g_W2h[(size_t)H1*H2], g_W2l[(size_t)H1*H2];
__device__ __nv_bfloat16 g_W3h[(size_t)H2*PIX], g_W3l[(size_t)H2*PIX];
__device__ __nv_bfloat16 g_h1h[(size_t)BN*H1], g_h1l[(size_t)BN*H1];
__device__ __nv_bfloat16 g_h2h[(size_t)BN*H2], g_h2l[(size_t)BN*H2];

__device__ __forceinline__ uint32_t sptr(const void* p) {
    return (uint32_t)__cvta_generic_to_shared(p);
}

// ---- hat[b,n,k,o] = sum_i weight[n,k,o,i] * incaps[b,k,i] ----
__global__ void k_hat(const float* __restrict__ incaps,
                      const float* __restrict__ weight) {
    int tid = blockIdx.x * blockDim.x + threadIdx.x;   // exact grid
    int o = tid & 15;
    int k = (tid >> 4) % NIN;
    int n = ((tid >> 4) / NIN) % NOUT;
    int b = tid / (16 * NIN * NOUT);
    const float4* w = (const float4*)(weight + ((size_t)(n*NIN + k)*DOUT + o)*DIN);
    const float4* x = (const float4*)(incaps + ((size_t)b*NIN + k)*DIN);
    float4 w0 = w[0], w1 = w[1], x0 = x[0], x1 = x[1];
    float s = w0.x*x0.x + w0.y*x0.y + w0.z*x0.z + w0.w*x0.w
            + w1.x*x1.x + w1.y*x1.y + w1.z*x1.z + w1.w*x1.w;
    g_hat[tid] = s;
}

// ---- split fp32 -> bf16 hi/lo ----
__global__ void k_split(const float* __restrict__ W,
                        __nv_bfloat16* __restrict__ Wh,
                        __nv_bfloat16* __restrict__ Wl, int n) {
    int i = blockIdx.x * blockDim.x + threadIdx.x;
    if (i < n) {
        float v = W[i];
        __nv_bfloat16 h = __float2bfloat16(v);
        Wh[i] = h;
        Wl[i] = __float2bfloat16(v - __bfloat162float(h));
    }
}

// ---- per (b,n): S=sum_k rc*hat ; outcaps=squash(S) ; bcoef[k]=outcaps.hat[k] ----
__global__ void k_routing(int use_rc, int do_b, float* __restrict__ out_vec) {
    int bn  = blockIdx.x;
    int tid = threadIdx.x;          // 256
    const float* hat = g_hat + (size_t)bn * NIN * DOUT;
    float rglob = use_rc ? g_r[bn] : 1.0f;

    float acc[16];
#pragma unroll
    for (int o = 0; o < 16; o++) acc[o] = 0.f;

    for (int k = tid; k < NIN; k += 256) {
        float rcv = use_rc ? g_c[(size_t)bn*NIN + k] * rglob : 1.0f;
        const float4* h4 = (const float4*)(hat + (size_t)k * 16);
        float4 a = h4[0], b4 = h4[1], c4 = h4[2], d4 = h4[3];
        acc[0]  += rcv*a.x;  acc[1]  += rcv*a.y;  acc[2]  += rcv*a.z;  acc[3]  += rcv*a.w;
        acc[4]  += rcv*b4.x; acc[5]  += rcv*b4.y; acc[6]  += rcv*b4.z; acc[7]  += rcv*b4.w;
        acc[8]  += rcv*c4.x; acc[9]  += rcv*c4.y; acc[10] += rcv*c4.z; acc[11] += rcv*c4.w;
        acc[12] += rcv*d4.x; acc[13] += rcv*d4.y; acc[14] += rcv*d4.z; acc[15] += rcv*d4.w;
    }

    __shared__ float red[256 * 16];
#pragma unroll
    for (int o = 0; o < 16; o++) red[tid*16 + o] = acc[o];
    __syncthreads();
    for (int s = 128; s > 0; s >>= 1) {
        if (tid < s) {
#pragma unroll
            for (int o = 0; o < 16; o++) red[tid*16 + o] += red[(tid+s)*16 + o];
        }
        __syncthreads();
    }

    __shared__ float oc[16];
    if (tid == 0) {
        float n2 = 0.f;
#pragma unroll
        for (int o = 0; o < 16; o++) { float v = red[o]; n2 += v*v; }
        float nrm   = sqrtf(n2);
        float scale = n2 / (1.f + n2) / (nrm + 1e-8f);
        float* dst = out_vec ? out_vec : g_outcaps;
#pragma unroll
        for (int o = 0; o < 16; o++) {
            float v = scale * red[o];
            oc[o] = v;
            dst[(size_t)bn*16 + o] = v;
        }
    }
    __syncthreads();
    if (!do_b) return;

    for (int k = tid; k < NIN; k += 256) {
        const float4* h4 = (const float4*)(hat + (size_t)k * 16);
        float4 a = h4[0], b4 = h4[1], c4 = h4[2], d4 = h4[3];
        float s = a.x*oc[0]  + a.y*oc[1]  + a.z*oc[2]  + a.w*oc[3]
                + b4.x*oc[4] + b4.y*oc[5] + b4.z*oc[6] + b4.w*oc[7]
                + c4.x*oc[8] + c4.y*oc[9] + c4.z*oc[10]+ c4.w*oc[11]
                + d4.x*oc[12]+ d4.y*oc[13]+ d4.z*oc[14]+ d4.w*oc[15];
        g_bcoef[(size_t)bn*NIN + k] = s;
    }
}

// ---- c = scale_coef(bcoef) over axis n (first 9), bg slot -> 0.5 ----
__global__ void k_scale_c() {
    int idx = blockIdx.x * blockDim.x + threadIdx.x;
    if (idx >= BATCH * NIN) return;
    int b = idx / NIN, k = idx % NIN;
    float v[9];
    float mn = 1e30f, mx = -1e30f;
#pragma unroll
    for (int n = 0; n < 9; n++) {
        float t = g_bcoef[((size_t)b*NOUT + n)*NIN + k];
        v[n] = t; mn = fminf(mn, t); mx = fmaxf(mx, t);
    }
    float denom = fmaxf(mx - mn, 1e-6f);
#pragma unroll
    for (int n = 0; n < 9; n++)
        g_c[((size_t)b*NOUT + n)*NIN + k] = fmaxf((v[n]-mn)/denom, 0.5f);
    g_c[((size_t)b*NOUT + 9)*NIN + k] = 0.5f;
}

// ---- layer1: only 16 inputs are nonzero (slot m); write h1 as bf16 hi/lo ----
__global__ void k_h1(const float* __restrict__ W1, const float* __restrict__ b1) {
    int r = blockIdx.x;                       // b*NOUT + m
    int j = blockIdx.y * blockDim.x + threadIdx.x;   // 0..511
    int m = r % NOUT;
    __shared__ float oc[16];
    if (threadIdx.x < 16) oc[threadIdx.x] = g_outcaps[(size_t)r*16 + threadIdx.x];
    __syncthreads();
    float s = b1[j];
#pragma unroll
    for (int d = 0; d < 16; d++)
        s += oc[d] * W1[(size_t)(m*16 + d)*H1 + j];
    float v = fmaxf(s, 0.f);
    __nv_bfloat16 h = __float2bfloat16(v);
    g_h1h[(size_t)r*H1 + j] = h;
    g_h1l[(size_t)r*H1 + j] = __float2bfloat16(v - __bfloat162float(h));
}

// =======================================================================
// Tensor-core GEMM, bf16 hi/lo 3-term compensation (~fp32 precision).
// C[M,N] = epi(A @ B + bias).  BM=128, BN=64, BK=32, 256 thr, 8 warps.
// Warp grid 4(M)x2(N): warp tile 32x32. mma.sync m16n8k16.
// EPI=1: relu -> Ch/Cl bf16 split. EPI=2: sigmoid -> Cf fp32.
// =======================================================================
#define MMA_BF16(d, a, b0r, b1r)                                            \
    asm volatile(                                                           \
        "mma.sync.aligned.m16n8k16.row.col.f32.bf16.bf16.f32 "              \
        "{%0,%1,%2,%3},{%4,%5,%6,%7},{%8,%9},{%0,%1,%2,%3};"                \
        : "+f"((d)[0]), "+f"((d)[1]), "+f"((d)[2]), "+f"((d)[3])            \
        : "r"((a)[0]), "r"((a)[1]), "r"((a)[2]), "r"((a)[3]),               \
          "r"(b0r), "r"(b1r))

#define LDSM_X4(r, addr)                                                    \
    asm volatile("ldmatrix.sync.aligned.m8n8.x4.shared.b16 {%0,%1,%2,%3}, [%4];" \
        : "=r"((r)[0]), "=r"((r)[1]), "=r"((r)[2]), "=r"((r)[3]) : "r"(addr))

#define LDSM_X4T(r, addr)                                                   \
    asm volatile("ldmatrix.sync.aligned.m8n8.x4.trans.shared.b16 {%0,%1,%2,%3}, [%4];" \
        : "=r"((r)[0]), "=r"((r)[1]), "=r"((r)[2]), "=r"((r)[3]) : "r"(addr))

#define AS_STRIDE 40   // 32 + 8 pad (80B row, ldmatrix conflict-free)
#define BS_STRIDE 72   // 64 + 8 pad (144B row, ldmatrix conflict-free)
#define GEMM_SMEM ((2*2*128*AS_STRIDE + 2*2*32*BS_STRIDE) * 2)

template <int EPI>
__global__ void __launch_bounds__(256) k_gemm_tc(
    const __nv_bfloat16* __restrict__ Ah, const __nv_bfloat16* __restrict__ Al,
    const __nv_bfloat16* __restrict__ Bh, const __nv_bfloat16* __restrict__ Bl,
    const float* __restrict__ bias,
    float* __restrict__ Cf, __nv_bfloat16* __restrict__ Ch,
    __nv_bfloat16* __restrict__ Cl, int N, int Kd)
{
    extern __shared__ char smem_raw[];
    __nv_bfloat16* As = (__nv_bfloat16*)smem_raw;               // [2][2][128][40]
    __nv_bfloat16* Bs = As + 2*2*128*AS_STRIDE;                  // [2][2][32][72]

    const int tid  = threadIdx.x;
    const int lane = tid & 31, warp = tid >> 5;
    const int row0 = blockIdx.y * 128, col0 = blockIdx.x * 64;
    const int m0 = (warp & 3) * 32, n0 = (warp >> 2) * 32;

    const int arow = tid >> 1, aks = (tid & 1) * 16;
    const int bkr  = tid >> 3, bnc = (tid & 7) * 8;

    float acc[2][4][4];
#pragma unroll
    for (int i = 0; i < 2; i++)
#pragma unroll
        for (int j = 0; j < 4; j++)
#pragma unroll
            for (int q = 0; q < 4; q++) acc[i][j][q] = 0.f;

    const int S = Kd >> 5;
    uint4 pA[4], pB[2];

    const __nv_bfloat16* Abase_h = Ah + (size_t)(row0 + arow) * Kd + aks;
    const __nv_bfloat16* Abase_l = Al + (size_t)(row0 + arow) * Kd + aks;
    const int bcol = col0 + bnc;

    // ---- load slab s into regs ----
    auto loadS = [&](int s) {
        const __nv_bfloat16* pa = Abase_h + s * 32;
        pA[0] = *(const uint4*)pa; pA[1] = *(const uint4*)(pa + 8);
        const __nv_bfloat16* pl = Abase_l + s * 32;
        pA[2] = *(const uint4*)pl; pA[3] = *(const uint4*)(pl + 8);
        const __nv_bfloat16* pbh = Bh + (size_t)(s * 32 + bkr) * N + bcol;
        const __nv_bfloat16* pbl = Bl + (size_t)(s * 32 + bkr) * N + bcol;
        if (bcol + 7 < N) {
            pB[0] = *(const uint4*)pbh; pB[1] = *(const uint4*)pbl;
        } else {
            __nv_bfloat16 th[8], tl[8];
#pragma unroll
            for (int j = 0; j < 8; j++) {
                bool ok = (bcol + j < N);
                th[j] = ok ? pbh[j] : __nv_bfloat16(0.f);
                tl[j] = ok ? pbl[j] : __nv_bfloat16(0.f);
            }
            pB[0] = *(const uint4*)th; pB[1] = *(const uint4*)tl;
        }
    };
    auto storeS = [&](int buf) {
        *(uint4*)&As[((buf*2 + 0)*128 + arow)*AS_STRIDE + aks]     = pA[0];
        *(uint4*)&As[((buf*2 + 0)*128 + arow)*AS_STRIDE + aks + 8] = pA[1];
        *(uint4*)&As[((buf*2 + 1)*128 + arow)*AS_STRIDE + aks]     = pA[2];
        *(uint4*)&As[((buf*2 + 1)*128 + arow)*AS_STRIDE + aks + 8] = pA[3];
        *(uint4*)&Bs[((buf*2 + 0)*32 + bkr)*BS_STRIDE + bnc] = pB[0];
        *(uint4*)&Bs[((buf*2 + 1)*32 + bkr)*BS_STRIDE + bnc] = pB[1];
    };

    const int afr = m0 + (lane & 15);          // A frag row (within tile)
    const int afc = (lane >> 4) * 8;           // A frag col offset in k16
    const int bfr = (lane & 15);               // B frag k row offset in k16
    const int bfc = n0 + (lane >> 4) * 8;      // B frag col

    loadS(0); storeS(0);
    __syncthreads();

    for (int s = 0; s < S; s++) {
        const int cur = s & 1;
        if (s + 1 < S) loadS(s + 1);

#pragma unroll
        for (int kf = 0; kf < 2; kf++) {
            uint32_t ahr[2][4], alr[2][4], bhr[2][4], blr[2][4];
#pragma unroll
            for (int im = 0; im < 2; im++) {
                uint32_t ad_h = sptr(&As[((cur*2+0)*128 + afr + im*16)*AS_STRIDE + kf*16 + afc]);
                LDSM_X4(ahr[im], ad_h);
                uint32_t ad_l = sptr(&As[((cur*2+1)*128 + afr + im*16)*AS_STRIDE + kf*16 + afc]);
                LDSM_X4(alr[im], ad_l);
            }
#pragma unroll
            for (int nb = 0; nb < 2; nb++) {
                uint32_t bd_h = sptr(&Bs[((cur*2+0)*32 + kf*16 + bfr)*BS_STRIDE + bfc + nb*16]);
                LDSM_X4T(bhr[nb], bd_h);
                uint32_t bd_l = sptr(&Bs[((cur*2+1)*32 + kf*16 + bfr)*BS_STRIDE + bfc + nb*16]);
                LDSM_X4T(blr[nb], bd_l);
            }
#pragma unroll
            for (int im = 0; im < 2; im++)
#pragma unroll
                for (int in = 0; in < 4; in++) {
                    const int nb = in >> 1, ns = in & 1;
                    uint32_t b0h = bhr[nb][ns*2], b1h = bhr[nb][ns*2+1];
                    uint32_t b0l = blr[nb][ns*2], b1l = blr[nb][ns*2+1];
                    MMA_BF16(acc[im][in], ahr[im], b0h, b1h);
                    MMA_BF16(acc[im][in], ahr[im], b0l, b1l);
                    MMA_BF16(acc[im][in], alr[im], b0h, b1h);
                }
        }

        if (s + 1 < S) storeS((s + 1) & 1);
        __syncthreads();
    }

    // ---- epilogue ----
#pragma unroll
    for (int im = 0; im < 2; im++)
#pragma unroll
        for (int in = 0; in < 4; in++) {
            int r = row0 + m0 + im*16 + (lane >> 2);
            int c = col0 + n0 + in*8 + (lane & 3) * 2;
            float bi0 = (c < N)     ? bias[c]     : 0.f;
            float bi1 = (c + 1 < N) ? bias[c + 1] : 0.f;
#pragma unroll
            for (int half = 0; half < 2; half++) {
                int rr = r + half * 8;
                float v0 = acc[im][in][half*2 + 0] + bi0;
                float v1 = acc[im][in][half*2 + 1] + bi1;
                if (EPI == 1) {
                    v0 = fmaxf(v0, 0.f); v1 = fmaxf(v1, 0.f);
                    if (c + 1 < N) {
                        __nv_bfloat16 h0 = __float2bfloat16(v0);
                        __nv_bfloat16 h1 = __float2bfloat16(v1);
                        __nv_bfloat162 hh; hh.x = h0; hh.y = h1;
                        *(__nv_bfloat162*)&Ch[(size_t)rr*N + c] = hh;
                        __nv_bfloat162 ll;
                        ll.x = __float2bfloat16(v0 - __bfloat162float(h0));
                        ll.y = __float2bfloat16(v1 - __bfloat162float(h1));
                        *(__nv_bfloat162*)&Cl[(size_t)rr*N + c] = ll;
                    }
                } else {
                    if (c < N)     Cf[(size_t)rr*N + c]     = 1.f / (1.f + __expf(-v0));
                    if (c + 1 < N) Cf[(size_t)rr*N + c + 1] = 1.f / (1.f + __expf(-v1));
                }
            }
        }
}

// ---- rscore[b,m] = -sum_p (x[b,p] - recon[b,m,p])^2 ----
__global__ void k_rscore(const float* __restrict__ x) {
    int r = blockIdx.x;
    int b = r / NOUT;
    int tid = threadIdx.x;
    float s = 0.f;
    for (int p = tid; p < PIX; p += 256) {
        float d = x[(size_t)b*PIX + p] - g_recon[(size_t)r*PIX + p];
        s += d * d;
    }
    __shared__ float red[256];
    red[tid] = s; __syncthreads();
    for (int st = 128; st > 0; st >>= 1) {
        if (tid < st) red[tid] += red[tid + st];
        __syncthreads();
    }
    if (tid == 0) g_rscore[r] = -red[0];
}

// ---- r = scale_coef(rscore) over m ----
__global__ void k_scale_r() {
    int b = threadIdx.x;
    if (b >= BATCH) return;
    float v[9];
    float mn = 1e30f, mx = -1e30f;
#pragma unroll
    for (int m = 0; m < 9; m++) {
        float t = g_rscore[b*NOUT + m];
        v[m] = t; mn = fminf(mn, t); mx = fmaxf(mx, t);
    }
    float denom = fmaxf(mx - mn, 1e-6f);
#pragma unroll
    for (int m = 0; m < 9; m++)
        g_r[b*NOUT + m] = fmaxf((v[m]-mn)/denom, 0.5f);
    g_r[b*NOUT + 9] = 0.5f;
}

extern "C" void kernel_launch(void* const* d_in, const int* in_sizes, int n_in,
                              void* d_out, int out_size) {
    const float* incaps = (const float*)d_in[0];
    const float* x      = (const float*)d_in[1];
    const float* weight = (const float*)d_in[2];
    const float* W1     = (const float*)d_in[3];
    const float* b1     = (const float*)d_in[4];
    const float* W2     = (const float*)d_in[5];
    const float* b2     = (const float*)d_in[6];
    const float* W3     = (const float*)d_in[7];
    const float* b3     = (const float*)d_in[8];
    float* out = (float*)d_out;

    cudaFuncSetAttribute(k_gemm_tc<1>, cudaFuncAttributeMaxDynamicSharedMemorySize, GEMM_SMEM);
    cudaFuncSetAttribute(k_gemm_tc<2>, cudaFuncAttributeMaxDynamicSharedMemorySize, GEMM_SMEM);

    __nv_bfloat16 *pW2h, *pW2l, *pW3h, *pW3l, *ph1h, *ph1l, *ph2h, *ph2l;
    float *p_recon;
    cudaGetSymbolAddress((void**)&pW2h, g_W2h);
    cudaGetSymbolAddress((void**)&pW2l, g_W2l);
    cudaGetSymbolAddress((void**)&pW3h, g_W3h);
    cudaGetSymbolAddress((void**)&pW3l, g_W3l);
    cudaGetSymbolAddress((void**)&ph1h, g_h1h);
    cudaGetSymbolAddress((void**)&ph1l, g_h1l);
    cudaGetSymbolAddress((void**)&ph2h, g_h2h);
    cudaGetSymbolAddress((void**)&ph2l, g_h2l);
    cudaGetSymbolAddress((void**)&p_recon, g_recon);

    int tot = BATCH * NOUT * NIN * DOUT;
    k_hat<<<tot/256, 256>>>(incaps, weight);
    k_split<<<(H1*H2 + 255)/256, 256>>>(W2, pW2h, pW2l, H1*H2);
    k_split<<<(H2*PIX + 255)/256, 256>>>(W3, pW3h, pW3l, H2*PIX);

    for (int it = 0; it < 2; it++) {
        k_routing<<<BN, 256>>>(it > 0 ? 1 : 0, 1, nullptr);
        k_scale_c<<<(BATCH*NIN + 255)/256, 256>>>();
        k_h1<<<dim3(BN, 2), 256>>>(W1, b1);
        k_gemm_tc<1><<<dim3(H2/64, BN/128), 256, GEMM_SMEM>>>(
            ph1h, ph1l, pW2h, pW2l, b2, nullptr, ph2h, ph2l, H2, H1);
        k_gemm_tc<2><<<dim3((PIX+63)/64, BN/128), 256, GEMM_SMEM>>>(
            ph2h, ph2l, pW3h, pW3l, b3, p_recon, nullptr, nullptr, PIX, H2);
        k_rscore<<<BN, 256>>>(x);
        k_scale_r<<<1, 128>>>();
    }
    k_routing<<<BN, 256>>>(1, 0, out);
}

// round 4
// speedup vs baseline: 2.6916x; 1.3199x over previous
#include <cuda_runtime.h>
#include <cuda_bf16.h>
#include <math.h>
#include <stdint.h>

#define BATCH 128
#define NOUT  10
#define NIN   1152
#define DOUT  16
#define DIN   8
#define H1    512
#define H2    1024
#define PIX   784
#define BN    (BATCH*NOUT)   // 1280

// ---- scratch (device globals; no allocations allowed) ----
__device__ float g_hat[(size_t)BATCH*NOUT*NIN*DOUT];  // 94.4 MB
__device__ float g_bcoef[(size_t)BATCH*NOUT*NIN];
__device__ float g_c[(size_t)BATCH*NOUT*NIN];
__device__ float g_outcaps[BN*DOUT];
__device__ float g_recon[(size_t)BN*PIX];
__device__ float g_r[BN];

// hi/lo bf16 split operands
__device__ __nv_bfloat16 g_W2h[(size_t)H1*H2], g_W2l[(size_t)H1*H2];
__device__ __nv_bfloat16 g_W3h[(size_t)H2*PIX], g_W3l[(size_t)H2*PIX];
__device__ __nv_bfloat16 g_h1h[(size_t)BN*H1], g_h1l[(size_t)BN*H1];
__device__ __nv_bfloat16 g_h2h[(size_t)BN*H2], g_h2l[(size_t)BN*H2];

__device__ __forceinline__ uint32_t sptr(const void* p) {
    return (uint32_t)__cvta_generic_to_shared(p);
}

// ---- hat[b,n,k,o] = sum_i weight[n,k,o,i] * incaps[b,k,i] ----
__global__ void k_hat(const float* __restrict__ incaps,
                      const float* __restrict__ weight) {
    int tid = blockIdx.x * blockDim.x + threadIdx.x;   // exact grid
    int o = tid & 15;
    int k = (tid >> 4) % NIN;
    int n = ((tid >> 4) / NIN) % NOUT;
    int b = tid / (16 * NIN * NOUT);
    const float4* w = (const float4*)(weight + ((size_t)(n*NIN + k)*DOUT + o)*DIN);
    const float4* x = (const float4*)(incaps + ((size_t)b*NIN + k)*DIN);
    float4 w0 = w[0], w1 = w[1], x0 = x[0], x1 = x[1];
    float s = w0.x*x0.x + w0.y*x0.y + w0.z*x0.z + w0.w*x0.w
            + w1.x*x1.x + w1.y*x1.y + w1.z*x1.z + w1.w*x1.w;
    g_hat[tid] = s;
}

// ---- split fp32 -> bf16 hi/lo ----
__global__ void k_split(const float* __restrict__ W,
                        __nv_bfloat16* __restrict__ Wh,
                        __nv_bfloat16* __restrict__ Wl, int n) {
    int i = blockIdx.x * blockDim.x + threadIdx.x;
    if (i < n) {
        float v = W[i];
        __nv_bfloat16 h = __float2bfloat16(v);
        Wh[i] = h;
        Wl[i] = __float2bfloat16(v - __bfloat162float(h));
    }
}

// =======================================================================
// Fused routing: one pass over hat per launch.
// Block = one (b,n). 384 threads. Each thread owns o-quad q=tid&3 and
// k rows krow+96*i (i<12): 12 independent float4 loads -> high MLP.
// hat tile staged to smem (only if do_b) so bcoef pass is smem-only.
// =======================================================================
#define RT_THREADS 384
#define RT_SMEM (NIN*DOUT*4)    // 73728 B

__global__ void __launch_bounds__(RT_THREADS) k_routing2(
        int use_rc, int do_b, float* __restrict__ out_vec) {
    extern __shared__ float4 tile4[];        // [NIN*4]
    __shared__ float red[12*16];
    __shared__ float s_oc[16];

    const int bn   = blockIdx.x;
    const int tid  = threadIdx.x;
    const int lane = tid & 31, warp = tid >> 5;
    const int q    = tid & 3;                // o-quad
    const int krow = tid >> 2;               // 0..95
    const float* hat = g_hat + (size_t)bn * NIN * DOUT;
    const float rglob = use_rc ? g_r[bn] : 1.0f;

    float rcv[12];
    if (use_rc) {
        const float* cb = g_c + (size_t)bn * NIN;
#pragma unroll
        for (int i = 0; i < 12; i++) rcv[i] = cb[krow + 96*i] * rglob;
    } else {
#pragma unroll
        for (int i = 0; i < 12; i++) rcv[i] = 1.0f;
    }

    float4 v[12];
#pragma unroll
    for (int i = 0; i < 12; i++)
        v[i] = *(const float4*)(hat + ((size_t)(krow + 96*i) * 16) + q * 4);

    float a0 = 0.f, a1 = 0.f, a2 = 0.f, a3 = 0.f;
#pragma unroll
    for (int i = 0; i < 12; i++) {
        if (do_b) tile4[tid + 384*i] = v[i];
        a0 += rcv[i] * v[i].x; a1 += rcv[i] * v[i].y;
        a2 += rcv[i] * v[i].z; a3 += rcv[i] * v[i].w;
    }

    // warp butterfly over lanes sharing q (xor 4, 8, 16)
#pragma unroll
    for (int m = 4; m <= 16; m <<= 1) {
        a0 += __shfl_xor_sync(0xffffffffu, a0, m);
        a1 += __shfl_xor_sync(0xffffffffu, a1, m);
        a2 += __shfl_xor_sync(0xffffffffu, a2, m);
        a3 += __shfl_xor_sync(0xffffffffu, a3, m);
    }
    if (lane < 4) {
        red[warp*16 + lane*4 + 0] = a0;
        red[warp*16 + lane*4 + 1] = a1;
        red[warp*16 + lane*4 + 2] = a2;
        red[warp*16 + lane*4 + 3] = a3;
    }
    __syncthreads();

    if (tid == 0) {
        float tot[16];
        float n2 = 0.f;
#pragma unroll
        for (int o = 0; o < 16; o++) {
            float s = 0.f;
#pragma unroll
            for (int w = 0; w < 12; w++) s += red[w*16 + o];
            tot[o] = s; n2 += s*s;
        }
        float nrm   = sqrtf(n2);
        float scale = n2 / (1.f + n2) / (nrm + 1e-8f);
        float* dst = out_vec ? out_vec : g_outcaps;
#pragma unroll
        for (int o = 0; o < 16; o++) {
            float vv = scale * tot[o];
            s_oc[o] = vv;
            dst[(size_t)bn*16 + o] = vv;
        }
    }
    __syncthreads();
    if (!do_b) return;

    const float oc0 = s_oc[q*4+0], oc1 = s_oc[q*4+1];
    const float oc2 = s_oc[q*4+2], oc3 = s_oc[q*4+3];
    float* bc = g_bcoef + (size_t)bn * NIN;
#pragma unroll
    for (int i = 0; i < 12; i++) {
        float4 h = tile4[tid + 384*i];
        float p = h.x*oc0 + h.y*oc1 + h.z*oc2 + h.w*oc3;
        p += __shfl_xor_sync(0xffffffffu, p, 1);
        p += __shfl_xor_sync(0xffffffffu, p, 2);
        if (q == 0) bc[krow + 96*i] = p;
    }
}

// ---- c = scale_coef(bcoef) over axis n (first 9), bg slot -> 0.5 ----
__global__ void k_scale_c() {
    int idx = blockIdx.x * blockDim.x + threadIdx.x;
    if (idx >= BATCH * NIN) return;
    int b = idx / NIN, k = idx % NIN;
    float v[9];
    float mn = 1e30f, mx = -1e30f;
#pragma unroll
    for (int n = 0; n < 9; n++) {
        float t = g_bcoef[((size_t)b*NOUT + n)*NIN + k];
        v[n] = t; mn = fminf(mn, t); mx = fmaxf(mx, t);
    }
    float denom = fmaxf(mx - mn, 1e-6f);
#pragma unroll
    for (int n = 0; n < 9; n++)
        g_c[((size_t)b*NOUT + n)*NIN + k] = fmaxf((v[n]-mn)/denom, 0.5f);
    g_c[((size_t)b*NOUT + 9)*NIN + k] = 0.5f;
}

// ---- layer1: only 16 inputs are nonzero (slot m); write h1 as bf16 hi/lo ----
__global__ void k_h1(const float* __restrict__ W1, const float* __restrict__ b1) {
    int r = blockIdx.x;                       // b*NOUT + m
    int j = blockIdx.y * blockDim.x + threadIdx.x;   // 0..511
    int m = r % NOUT;
    __shared__ float oc[16];
    if (threadIdx.x < 16) oc[threadIdx.x] = g_outcaps[(size_t)r*16 + threadIdx.x];
    __syncthreads();
    float s = b1[j];
#pragma unroll
    for (int d = 0; d < 16; d++)
        s += oc[d] * W1[(size_t)(m*16 + d)*H1 + j];
    float v = fmaxf(s, 0.f);
    __nv_bfloat16 h = __float2bfloat16(v);
    g_h1h[(size_t)r*H1 + j] = h;
    g_h1l[(size_t)r*H1 + j] = __float2bfloat16(v - __bfloat162float(h));
}

// =======================================================================
// Tensor-core GEMM, bf16 hi/lo 3-term compensation (~fp32 precision).
// =======================================================================
#define MMA_BF16(d, a, b0r, b1r)                                            \
    asm volatile(                                                           \
        "mma.sync.aligned.m16n8k16.row.col.f32.bf16.bf16.f32 "              \
        "{%0,%1,%2,%3},{%4,%5,%6,%7},{%8,%9},{%0,%1,%2,%3};"                \
        : "+f"((d)[0]), "+f"((d)[1]), "+f"((d)[2]), "+f"((d)[3])            \
        : "r"((a)[0]), "r"((a)[1]), "r"((a)[2]), "r"((a)[3]),               \
          "r"(b0r), "r"(b1r))

#define LDSM_X4(r, addr)                                                    \
    asm volatile("ldmatrix.sync.aligned.m8n8.x4.shared.b16 {%0,%1,%2,%3}, [%4];" \
        : "=r"((r)[0]), "=r"((r)[1]), "=r"((r)[2]), "=r"((r)[3]) : "r"(addr))

#define LDSM_X4T(r, addr)                                                   \
    asm volatile("ldmatrix.sync.aligned.m8n8.x4.trans.shared.b16 {%0,%1,%2,%3}, [%4];" \
        : "=r"((r)[0]), "=r"((r)[1]), "=r"((r)[2]), "=r"((r)[3]) : "r"(addr))

#define AS_STRIDE 40   // 32 + 8 pad
#define BS_STRIDE 72   // 64 + 8 pad
#define GEMM_SMEM ((2*2*128*AS_STRIDE + 2*2*32*BS_STRIDE) * 2)

template <int EPI>
__global__ void __launch_bounds__(256) k_gemm_tc(
    const __nv_bfloat16* __restrict__ Ah, const __nv_bfloat16* __restrict__ Al,
    const __nv_bfloat16* __restrict__ Bh, const __nv_bfloat16* __restrict__ Bl,
    const float* __restrict__ bias,
    float* __restrict__ Cf, __nv_bfloat16* __restrict__ Ch,
    __nv_bfloat16* __restrict__ Cl, int N, int Kd)
{
    extern __shared__ char smem_raw[];
    __nv_bfloat16* As = (__nv_bfloat16*)smem_raw;
    __nv_bfloat16* Bs = As + 2*2*128*AS_STRIDE;

    const int tid  = threadIdx.x;
    const int lane = tid & 31, warp = tid >> 5;
    const int row0 = blockIdx.y * 128, col0 = blockIdx.x * 64;
    const int m0 = (warp & 3) * 32, n0 = (warp >> 2) * 32;

    const int arow = tid >> 1, aks = (tid & 1) * 16;
    const int bkr  = tid >> 3, bnc = (tid & 7) * 8;

    float acc[2][4][4];
#pragma unroll
    for (int i = 0; i < 2; i++)
#pragma unroll
        for (int j = 0; j < 4; j++)
#pragma unroll
            for (int q = 0; q < 4; q++) acc[i][j][q] = 0.f;

    const int S = Kd >> 5;
    uint4 pA[4], pB[2];

    const __nv_bfloat16* Abase_h = Ah + (size_t)(row0 + arow) * Kd + aks;
    const __nv_bfloat16* Abase_l = Al + (size_t)(row0 + arow) * Kd + aks;
    const int bcol = col0 + bnc;

    auto loadS = [&](int s) {
        const __nv_bfloat16* pa = Abase_h + s * 32;
        pA[0] = *(const uint4*)pa; pA[1] = *(const uint4*)(pa + 8);
        const __nv_bfloat16* pl = Abase_l + s * 32;
        pA[2] = *(const uint4*)pl; pA[3] = *(const uint4*)(pl + 8);
        const __nv_bfloat16* pbh = Bh + (size_t)(s * 32 + bkr) * N + bcol;
        const __nv_bfloat16* pbl = Bl + (size_t)(s * 32 + bkr) * N + bcol;
        if (bcol + 7 < N) {
            pB[0] = *(const uint4*)pbh; pB[1] = *(const uint4*)pbl;
        } else {
            __nv_bfloat16 th[8], tl[8];
#pragma unroll
            for (int j = 0; j < 8; j++) {
                bool ok = (bcol + j < N);
                th[j] = ok ? pbh[j] : __nv_bfloat16(0.f);
                tl[j] = ok ? pbl[j] : __nv_bfloat16(0.f);
            }
            pB[0] = *(const uint4*)th; pB[1] = *(const uint4*)tl;
        }
    };
    auto storeS = [&](int buf) {
        *(uint4*)&As[((buf*2 + 0)*128 + arow)*AS_STRIDE + aks]     = pA[0];
        *(uint4*)&As[((buf*2 + 0)*128 + arow)*AS_STRIDE + aks + 8] = pA[1];
        *(uint4*)&As[((buf*2 + 1)*128 + arow)*AS_STRIDE + aks]     = pA[2];
        *(uint4*)&As[((buf*2 + 1)*128 + arow)*AS_STRIDE + aks + 8] = pA[3];
        *(uint4*)&Bs[((buf*2 + 0)*32 + bkr)*BS_STRIDE + bnc] = pB[0];
        *(uint4*)&Bs[((buf*2 + 1)*32 + bkr)*BS_STRIDE + bnc] = pB[1];
    };

    const int afr = m0 + (lane & 15);
    const int afc = (lane >> 4) * 8;
    const int bfr = (lane & 15);
    const int bfc = n0 + (lane >> 4) * 8;

    loadS(0); storeS(0);
    __syncthreads();

    for (int s = 0; s < S; s++) {
        const int cur = s & 1;
        if (s + 1 < S) loadS(s + 1);

#pragma unroll
        for (int kf = 0; kf < 2; kf++) {
            uint32_t ahr[2][4], alr[2][4], bhr[2][4], blr[2][4];
#pragma unroll
            for (int im = 0; im < 2; im++) {
                uint32_t ad_h = sptr(&As[((cur*2+0)*128 + afr + im*16)*AS_STRIDE + kf*16 + afc]);
                LDSM_X4(ahr[im], ad_h);
                uint32_t ad_l = sptr(&As[((cur*2+1)*128 + afr + im*16)*AS_STRIDE + kf*16 + afc]);
                LDSM_X4(alr[im], ad_l);
            }
#pragma unroll
            for (int nb = 0; nb < 2; nb++) {
                uint32_t bd_h = sptr(&Bs[((cur*2+0)*32 + kf*16 + bfr)*BS_STRIDE + bfc + nb*16]);
                LDSM_X4T(bhr[nb], bd_h);
                uint32_t bd_l = sptr(&Bs[((cur*2+1)*32 + kf*16 + bfr)*BS_STRIDE + bfc + nb*16]);
                LDSM_X4T(blr[nb], bd_l);
            }
#pragma unroll
            for (int im = 0; im < 2; im++)
#pragma unroll
                for (int in = 0; in < 4; in++) {
                    const int nb = in >> 1, ns = in & 1;
                    uint32_t b0h = bhr[nb][ns*2], b1h = bhr[nb][ns*2+1];
                    uint32_t b0l = blr[nb][ns*2], b1l = blr[nb][ns*2+1];
                    MMA_BF16(acc[im][in], ahr[im], b0h, b1h);
                    MMA_BF16(acc[im][in], ahr[im], b0l, b1l);
                    MMA_BF16(acc[im][in], alr[im], b0h, b1h);
                }
        }

        if (s + 1 < S) storeS((s + 1) & 1);
        __syncthreads();
    }

#pragma unroll
    for (int im = 0; im < 2; im++)
#pragma unroll
        for (int in = 0; in < 4; in++) {
            int r = row0 + m0 + im*16 + (lane >> 2);
            int c = col0 + n0 + in*8 + (lane & 3) * 2;
            float bi0 = (c < N)     ? bias[c]     : 0.f;
            float bi1 = (c + 1 < N) ? bias[c + 1] : 0.f;
#pragma unroll
            for (int half = 0; half < 2; half++) {
                int rr = r + half * 8;
                float v0 = acc[im][in][half*2 + 0] + bi0;
                float v1 = acc[im][in][half*2 + 1] + bi1;
                if (EPI == 1) {
                    v0 = fmaxf(v0, 0.f); v1 = fmaxf(v1, 0.f);
                    if (c + 1 < N) {
                        __nv_bfloat16 h0 = __float2bfloat16(v0);
                        __nv_bfloat16 h1 = __float2bfloat16(v1);
                        __nv_bfloat162 hh; hh.x = h0; hh.y = h1;
                        *(__nv_bfloat162*)&Ch[(size_t)rr*N + c] = hh;
                        __nv_bfloat162 ll;
                        ll.x = __float2bfloat16(v0 - __bfloat162float(h0));
                        ll.y = __float2bfloat16(v1 - __bfloat162float(h1));
                        *(__nv_bfloat162*)&Cl[(size_t)rr*N + c] = ll;
                    }
                } else {
                    if (c < N)     Cf[(size_t)rr*N + c]     = 1.f / (1.f + __expf(-v0));
                    if (c + 1 < N) Cf[(size_t)rr*N + c + 1] = 1.f / (1.f + __expf(-v1));
                }
            }
        }
}

// ---- fused rscore + scale_r: one block per batch item ----
__global__ void k_rscale(const float* __restrict__ x) {
    __shared__ float xs[PIX];
    __shared__ float wred[8];
    __shared__ float rs[NOUT];
    int b = blockIdx.x;
    int tid = threadIdx.x;           // 256
    int lane = tid & 31, warp = tid >> 5;
    for (int p = tid; p < PIX; p += 256) xs[p] = x[(size_t)b*PIX + p];
    __syncthreads();

    for (int m = 0; m < NOUT; m++) {
        const float* rec = g_recon + ((size_t)(b*NOUT + m)) * PIX;
        float s = 0.f;
        for (int p = tid; p < PIX; p += 256) {
            float d = xs[p] - rec[p];
            s += d * d;
        }
#pragma unroll
        for (int o = 16; o > 0; o >>= 1) s += __shfl_xor_sync(0xffffffffu, s, o);
        if (lane == 0) wred[warp] = s;
        __syncthreads();
        if (tid == 0) {
            float t = 0.f;
#pragma unroll
            for (int w = 0; w < 8; w++) t += wred[w];
            rs[m] = -t;
        }
        __syncthreads();
    }
    if (tid == 0) {
        float mn = 1e30f, mx = -1e30f;
#pragma unroll
        for (int m = 0; m < 9; m++) { mn = fminf(mn, rs[m]); mx = fmaxf(mx, rs[m]); }
        float denom = fmaxf(mx - mn, 1e-6f);
#pragma unroll
        for (int m = 0; m < 9; m++)
            g_r[b*NOUT + m] = fmaxf((rs[m]-mn)/denom, 0.5f);
        g_r[b*NOUT + 9] = 0.5f;
    }
}

extern "C" void kernel_launch(void* const* d_in, const int* in_sizes, int n_in,
                              void* d_out, int out_size) {
    const float* incaps = (const float*)d_in[0];
    const float* x      = (const float*)d_in[1];
    const float* weight = (const float*)d_in[2];
    const float* W1     = (const float*)d_in[3];
    const float* b1     = (const float*)d_in[4];
    const float* W2     = (const float*)d_in[5];
    const float* b2     = (const float*)d_in[6];
    const float* W3     = (const float*)d_in[7];
    const float* b3     = (const float*)d_in[8];
    float* out = (float*)d_out;

    cudaFuncSetAttribute(k_gemm_tc<1>, cudaFuncAttributeMaxDynamicSharedMemorySize, GEMM_SMEM);
    cudaFuncSetAttribute(k_gemm_tc<2>, cudaFuncAttributeMaxDynamicSharedMemorySize, GEMM_SMEM);
    cudaFuncSetAttribute(k_routing2, cudaFuncAttributeMaxDynamicSharedMemorySize, RT_SMEM);

    __nv_bfloat16 *pW2h, *pW2l, *pW3h, *pW3l, *ph1h, *ph1l, *ph2h, *ph2l;
    float *p_recon;
    cudaGetSymbolAddress((void**)&pW2h, g_W2h);
    cudaGetSymbolAddress((void**)&pW2l, g_W2l);
    cudaGetSymbolAddress((void**)&pW3h, g_W3h);
    cudaGetSymbolAddress((void**)&pW3l, g_W3l);
    cudaGetSymbolAddress((void**)&ph1h, g_h1h);
    cudaGetSymbolAddress((void**)&ph1l, g_h1l);
    cudaGetSymbolAddress((void**)&ph2h, g_h2h);
    cudaGetSymbolAddress((void**)&ph2l, g_h2l);
    cudaGetSymbolAddress((void**)&p_recon, g_recon);

    int tot = BATCH * NOUT * NIN * DOUT;
    k_hat<<<tot/256, 256>>>(incaps, weight);
    k_split<<<(H1*H2 + 255)/256, 256>>>(W2, pW2h, pW2l, H1*H2);
    k_split<<<(H2*PIX + 255)/256, 256>>>(W3, pW3h, pW3l, H2*PIX);

    for (int it = 0; it < 2; it++) {
        k_routing2<<<BN, RT_THREADS, RT_SMEM>>>(it > 0 ? 1 : 0, 1, nullptr);
        k_scale_c<<<(BATCH*NIN + 255)/256, 256>>>();
        k_h1<<<dim3(BN, 2), 256>>>(W1, b1);
        k_gemm_tc<1><<<dim3(H2/64, BN/128), 256, GEMM_SMEM>>>(
            ph1h, ph1l, pW2h, pW2l, b2, nullptr, ph2h, ph2l, H2, H1);
        k_gemm_tc<2><<<dim3((PIX+63)/64, BN/128), 256, GEMM_SMEM>>>(
            ph2h, ph2l, pW3h, pW3l, b3, p_recon, nullptr, nullptr, PIX, H2);
        k_rscale<<<BATCH, 256>>>(x);
    }
    k_routing2<<<BN, RT_THREADS, RT_SMEM>>>(1, 0, out);
}

// round 5
// speedup vs baseline: 2.9666x; 1.1022x over previous
#include <cuda_runtime.h>
#include <cuda_bf16.h>
#include <math.h>
#include <stdint.h>

#define BATCH 128
#define NOUT  10
#define NIN   1152
#define DOUT  16
#define DIN   8
#define H1    512
#define H2    1024
#define PIX   784
#define BN    (BATCH*NOUT)   // 1280
#define NCB2  13             // gemm2 column blocks = ceil(784/64)

// ---- scratch (device globals; no allocations allowed) ----
__device__ float g_hat[(size_t)BATCH*NOUT*NIN*DOUT];  // 94.4 MB
__device__ float g_bcoef[(size_t)BATCH*NOUT*NIN];
__device__ float g_c[(size_t)BATCH*NOUT*NIN];
__device__ float g_outcaps[BN*DOUT];
__device__ float g_recon[(size_t)BN*PIX];
__device__ float g_rsp[NCB2*BN];     // rscore partials [colblk][row]

// hi/lo bf16 split operands
__device__ __nv_bfloat16 g_W2h[(size_t)H1*H2], g_W2l[(size_t)H1*H2];
__device__ __nv_bfloat16 g_W3h[(size_t)H2*PIX], g_W3l[(size_t)H2*PIX];
__device__ __nv_bfloat16 g_h1h[(size_t)BN*H1], g_h1l[(size_t)BN*H1];
__device__ __nv_bfloat16 g_h2h[(size_t)BN*H2], g_h2l[(size_t)BN*H2];

__device__ __forceinline__ uint32_t sptr(const void* p) {
    return (uint32_t)__cvta_generic_to_shared(p);
}

// ---- hat[b,n,k,o] = sum_i weight[n,k,o,i] * incaps[b,k,i] ----
__global__ void k_hat(const float* __restrict__ incaps,
                      const float* __restrict__ weight) {
    int tid = blockIdx.x * blockDim.x + threadIdx.x;   // exact grid
    int o = tid & 15;
    int k = (tid >> 4) % NIN;
    int n = ((tid >> 4) / NIN) % NOUT;
    int b = tid / (16 * NIN * NOUT);
    const float4* w = (const float4*)(weight + ((size_t)(n*NIN + k)*DOUT + o)*DIN);
    const float4* x = (const float4*)(incaps + ((size_t)b*NIN + k)*DIN);
    float4 w0 = w[0], w1 = w[1], x0 = x[0], x1 = x[1];
    float s = w0.x*x0.x + w0.y*x0.y + w0.z*x0.z + w0.w*x0.w
            + w1.x*x1.x + w1.y*x1.y + w1.z*x1.z + w1.w*x1.w;
    g_hat[tid] = s;
}

// ---- split W2 and W3 (concatenated) fp32 -> bf16 hi/lo ----
__global__ void k_split2(const float* __restrict__ W2, const float* __restrict__ W3) {
    int i = blockIdx.x * blockDim.x + threadIdx.x;
    const int n2 = H1*H2;
    const int nt = n2 + H2*PIX;
    if (i >= nt) return;
    float v; __nv_bfloat16 *ph, *pl; int j;
    if (i < n2) { v = W2[i]; j = i;       ph = g_W2h; pl = g_W2l; }
    else        { j = i - n2; v = W3[j];  ph = g_W3h; pl = g_W3l; }
    __nv_bfloat16 h = __float2bfloat16(v);
    ph[j] = h;
    pl[j] = __float2bfloat16(v - __bfloat162float(h));
}

// =======================================================================
// Fused routing: one pass over hat. Block = one (b,n), 384 threads.
// Also computes r = scale_coef(rscore) inline from g_rsp partials.
// hat tile staged to smem as bf16 (only if do_b) for the bcoef pass.
// =======================================================================
#define RT_THREADS 384
#define RT_SMEM (NIN*DOUT*2)    // 36864 B (bf16 staging)

__global__ void __launch_bounds__(RT_THREADS) k_routing2(
        int use_rc, int do_b, float* __restrict__ out_vec) {
    extern __shared__ uint2 tile2[];         // [NIN*4] bf16x4 packs
    __shared__ float red[12*16];
    __shared__ float s_oc[16];
    __shared__ float s_rglob;

    const int bn   = blockIdx.x;
    const int tid  = threadIdx.x;
    const int lane = tid & 31, warp = tid >> 5;
    const int q    = tid & 3;                // o-quad
    const int krow = tid >> 2;               // 0..95
    const float* hat = g_hat + (size_t)bn * NIN * DOUT;

    if (use_rc) {
        if (tid == 0) {
            int b = bn / NOUT, n = bn % NOUT;
            float rs[NOUT];
#pragma unroll
            for (int m = 0; m < NOUT; m++) {
                float s = 0.f;
#pragma unroll
                for (int cb = 0; cb < NCB2; cb++) s += g_rsp[cb*BN + b*NOUT + m];
                rs[m] = -s;
            }
            float mn = 1e30f, mx = -1e30f;
#pragma unroll
            for (int m = 0; m < 9; m++) { mn = fminf(mn, rs[m]); mx = fmaxf(mx, rs[m]); }
            float denom = fmaxf(mx - mn, 1e-6f);
            s_rglob = (n == 9) ? 0.5f : fmaxf((rs[n]-mn)/denom, 0.5f);
        }
        __syncthreads();
    }
    const float rglob = use_rc ? s_rglob : 1.0f;

    float rcv[12];
    if (use_rc) {
        const float* cb = g_c + (size_t)bn * NIN;
#pragma unroll
        for (int i = 0; i < 12; i++) rcv[i] = cb[krow + 96*i] * rglob;
    } else {
#pragma unroll
        for (int i = 0; i < 12; i++) rcv[i] = 1.0f;
    }

    float4 v[12];
#pragma unroll
    for (int i = 0; i < 12; i++)
        v[i] = *(const float4*)(hat + ((size_t)(krow + 96*i) * 16) + q * 4);

    float a0 = 0.f, a1 = 0.f, a2 = 0.f, a3 = 0.f;
#pragma unroll
    for (int i = 0; i < 12; i++) {
        if (do_b) {
            __nv_bfloat162 lo = __floats2bfloat162_rn(v[i].x, v[i].y);
            __nv_bfloat162 hi = __floats2bfloat162_rn(v[i].z, v[i].w);
            uint2 pk;
            pk.x = *(uint32_t*)&lo; pk.y = *(uint32_t*)&hi;
            tile2[tid + 384*i] = pk;
        }
        a0 += rcv[i] * v[i].x; a1 += rcv[i] * v[i].y;
        a2 += rcv[i] * v[i].z; a3 += rcv[i] * v[i].w;
    }

    // warp butterfly over lanes sharing q (xor 4, 8, 16)
#pragma unroll
    for (int m = 4; m <= 16; m <<= 1) {
        a0 += __shfl_xor_sync(0xffffffffu, a0, m);
        a1 += __shfl_xor_sync(0xffffffffu, a1, m);
        a2 += __shfl_xor_sync(0xffffffffu, a2, m);
        a3 += __shfl_xor_sync(0xffffffffu, a3, m);
    }
    if (lane < 4) {
        red[warp*16 + lane*4 + 0] = a0;
        red[warp*16 + lane*4 + 1] = a1;
        red[warp*16 + lane*4 + 2] = a2;
        red[warp*16 + lane*4 + 3] = a3;
    }
    __syncthreads();

    if (tid == 0) {
        float tot[16];
        float n2 = 0.f;
#pragma unroll
        for (int o = 0; o < 16; o++) {
            float s = 0.f;
#pragma unroll
            for (int w = 0; w < 12; w++) s += red[w*16 + o];
            tot[o] = s; n2 += s*s;
        }
        float nrm   = sqrtf(n2);
        float scale = n2 / (1.f + n2) / (nrm + 1e-8f);
        float* dst = out_vec ? out_vec : g_outcaps;
#pragma unroll
        for (int o = 0; o < 16; o++) {
            float vv = scale * tot[o];
            s_oc[o] = vv;
            dst[(size_t)bn*16 + o] = vv;
        }
    }
    __syncthreads();
    if (!do_b) return;

    const float oc0 = s_oc[q*4+0], oc1 = s_oc[q*4+1];
    const float oc2 = s_oc[q*4+2], oc3 = s_oc[q*4+3];
    float* bc = g_bcoef + (size_t)bn * NIN;
#pragma unroll
    for (int i = 0; i < 12; i++) {
        uint2 pk = tile2[tid + 384*i];
        __nv_bfloat162 lo = *(__nv_bfloat162*)&pk.x;
        __nv_bfloat162 hi = *(__nv_bfloat162*)&pk.y;
        float p = __low2float(lo)*oc0 + __high2float(lo)*oc1
                + __low2float(hi)*oc2 + __high2float(hi)*oc3;
        p += __shfl_xor_sync(0xffffffffu, p, 1);
        p += __shfl_xor_sync(0xffffffffu, p, 2);
        if (q == 0) bc[krow + 96*i] = p;
    }
}

// ---- c = scale_coef(bcoef) over axis n (first 9), bg slot -> 0.5 ----
__global__ void k_scale_c() {
    int idx = blockIdx.x * blockDim.x + threadIdx.x;
    if (idx >= BATCH * NIN) return;
    int b = idx / NIN, k = idx % NIN;
    float v[9];
    float mn = 1e30f, mx = -1e30f;
#pragma unroll
    for (int n = 0; n < 9; n++) {
        float t = g_bcoef[((size_t)b*NOUT + n)*NIN + k];
        v[n] = t; mn = fminf(mn, t); mx = fmaxf(mx, t);
    }
    float denom = fmaxf(mx - mn, 1e-6f);
#pragma unroll
    for (int n = 0; n < 9; n++)
        g_c[((size_t)b*NOUT + n)*NIN + k] = fmaxf((v[n]-mn)/denom, 0.5f);
    g_c[((size_t)b*NOUT + 9)*NIN + k] = 0.5f;
}

// ---- layer1: only 16 inputs are nonzero (slot m); write h1 as bf16 hi/lo ----
__global__ void k_h1(const float* __restrict__ W1, const float* __restrict__ b1) {
    int r = blockIdx.x;                       // b*NOUT + m
    int j = blockIdx.y * blockDim.x + threadIdx.x;   // 0..511
    int m = r % NOUT;
    __shared__ float oc[16];
    if (threadIdx.x < 16) oc[threadIdx.x] = g_outcaps[(size_t)r*16 + threadIdx.x];
    __syncthreads();
    float s = b1[j];
#pragma unroll
    for (int d = 0; d < 16; d++)
        s += oc[d] * W1[(size_t)(m*16 + d)*H1 + j];
    float v = fmaxf(s, 0.f);
    __nv_bfloat16 h = __float2bfloat16(v);
    g_h1h[(size_t)r*H1 + j] = h;
    g_h1l[(size_t)r*H1 + j] = __float2bfloat16(v - __bfloat162float(h));
}

// =======================================================================
// Tensor-core GEMM, bf16 hi/lo 3-term compensation (~fp32 precision).
// EPI=1: relu -> Ch/Cl bf16 split.
// EPI=2: sigmoid -> Cf fp32 + fused rscore partials to g_rsp (fixed order).
// =======================================================================
#define MMA_BF16(d, a, b0r, b1r)                                            \
    asm volatile(                                                           \
        "mma.sync.aligned.m16n8k16.row.col.f32.bf16.bf16.f32 "              \
        "{%0,%1,%2,%3},{%4,%5,%6,%7},{%8,%9},{%0,%1,%2,%3};"                \
        : "+f"((d)[0]), "+f"((d)[1]), "+f"((d)[2]), "+f"((d)[3])            \
        : "r"((a)[0]), "r"((a)[1]), "r"((a)[2]), "r"((a)[3]),               \
          "r"(b0r), "r"(b1r))

#define LDSM_X4(r, addr)                                                    \
    asm volatile("ldmatrix.sync.aligned.m8n8.x4.shared.b16 {%0,%1,%2,%3}, [%4];" \
        : "=r"((r)[0]), "=r"((r)[1]), "=r"((r)[2]), "=r"((r)[3]) : "r"(addr))

#define LDSM_X4T(r, addr)                                                   \
    asm volatile("ldmatrix.sync.aligned.m8n8.x4.trans.shared.b16 {%0,%1,%2,%3}, [%4];" \
        : "=r"((r)[0]), "=r"((r)[1]), "=r"((r)[2]), "=r"((r)[3]) : "r"(addr))

#define AS_STRIDE 40   // 32 + 8 pad
#define BS_STRIDE 72   // 64 + 8 pad
#define GEMM_SMEM ((2*2*128*AS_STRIDE + 2*2*32*BS_STRIDE) * 2)

template <int EPI>
__global__ void __launch_bounds__(256) k_gemm_tc(
    const __nv_bfloat16* __restrict__ Ah, const __nv_bfloat16* __restrict__ Al,
    const __nv_bfloat16* __restrict__ Bh, const __nv_bfloat16* __restrict__ Bl,
    const float* __restrict__ bias,
    float* __restrict__ Cf, __nv_bfloat16* __restrict__ Ch,
    __nv_bfloat16* __restrict__ Cl,
    const float* __restrict__ xin,          // EPI==2 only
    int N, int Kd)
{
    extern __shared__ char smem_raw[];
    __nv_bfloat16* As = (__nv_bfloat16*)smem_raw;
    __nv_bfloat16* Bs = As + 2*2*128*AS_STRIDE;
    __shared__ float s_rs[128][2];

    const int tid  = threadIdx.x;
    const int lane = tid & 31, warp = tid >> 5;
    const int row0 = blockIdx.y * 128, col0 = blockIdx.x * 64;
    const int m0 = (warp & 3) * 32, n0 = (warp >> 2) * 32;

    const int arow = tid >> 1, aks = (tid & 1) * 16;
    const int bkr  = tid >> 3, bnc = (tid & 7) * 8;

    float acc[2][4][4];
#pragma unroll
    for (int i = 0; i < 2; i++)
#pragma unroll
        for (int j = 0; j < 4; j++)
#pragma unroll
            for (int q = 0; q < 4; q++) acc[i][j][q] = 0.f;

    const int S = Kd >> 5;
    uint4 pA[4], pB[2];

    const __nv_bfloat16* Abase_h = Ah + (size_t)(row0 + arow) * Kd + aks;
    const __nv_bfloat16* Abase_l = Al + (size_t)(row0 + arow) * Kd + aks;
    const int bcol = col0 + bnc;

    auto loadS = [&](int s) {
        const __nv_bfloat16* pa = Abase_h + s * 32;
        pA[0] = *(const uint4*)pa; pA[1] = *(const uint4*)(pa + 8);
        const __nv_bfloat16* pl = Abase_l + s * 32;
        pA[2] = *(const uint4*)pl; pA[3] = *(const uint4*)(pl + 8);
        const __nv_bfloat16* pbh = Bh + (size_t)(s * 32 + bkr) * N + bcol;
        const __nv_bfloat16* pbl = Bl + (size_t)(s * 32 + bkr) * N + bcol;
        if (bcol + 7 < N) {
            pB[0] = *(const uint4*)pbh; pB[1] = *(const uint4*)pbl;
        } else {
            __nv_bfloat16 th[8], tl[8];
#pragma unroll
            for (int j = 0; j < 8; j++) {
                bool ok = (bcol + j < N);
                th[j] = ok ? pbh[j] : __nv_bfloat16(0.f);
                tl[j] = ok ? pbl[j] : __nv_bfloat16(0.f);
            }
            pB[0] = *(const uint4*)th; pB[1] = *(const uint4*)tl;
        }
    };
    auto storeS = [&](int buf) {
        *(uint4*)&As[((buf*2 + 0)*128 + arow)*AS_STRIDE + aks]     = pA[0];
        *(uint4*)&As[((buf*2 + 0)*128 + arow)*AS_STRIDE + aks + 8] = pA[1];
        *(uint4*)&As[((buf*2 + 1)*128 + arow)*AS_STRIDE + aks]     = pA[2];
        *(uint4*)&As[((buf*2 + 1)*128 + arow)*AS_STRIDE + aks + 8] = pA[3];
        *(uint4*)&Bs[((buf*2 + 0)*32 + bkr)*BS_STRIDE + bnc] = pB[0];
        *(uint4*)&Bs[((buf*2 + 1)*32 + bkr)*BS_STRIDE + bnc] = pB[1];
    };

    const int afr = m0 + (lane & 15);
    const int afc = (lane >> 4) * 8;
    const int bfr = (lane & 15);
    const int bfc = n0 + (lane >> 4) * 8;

    loadS(0); storeS(0);
    __syncthreads();

    for (int s = 0; s < S; s++) {
        const int cur = s & 1;
        if (s + 1 < S) loadS(s + 1);

#pragma unroll
        for (int kf = 0; kf < 2; kf++) {
            uint32_t ahr[2][4], alr[2][4], bhr[2][4], blr[2][4];
#pragma unroll
            for (int im = 0; im < 2; im++) {
                uint32_t ad_h = sptr(&As[((cur*2+0)*128 + afr + im*16)*AS_STRIDE + kf*16 + afc]);
                LDSM_X4(ahr[im], ad_h);
                uint32_t ad_l = sptr(&As[((cur*2+1)*128 + afr + im*16)*AS_STRIDE + kf*16 + afc]);
                LDSM_X4(alr[im], ad_l);
            }
#pragma unroll
            for (int nb = 0; nb < 2; nb++) {
                uint32_t bd_h = sptr(&Bs[((cur*2+0)*32 + kf*16 + bfr)*BS_STRIDE + bfc + nb*16]);
                LDSM_X4T(bhr[nb], bd_h);
                uint32_t bd_l = sptr(&Bs[((cur*2+1)*32 + kf*16 + bfr)*BS_STRIDE + bfc + nb*16]);
                LDSM_X4T(blr[nb], bd_l);
            }
#pragma unroll
            for (int im = 0; im < 2; im++)
#pragma unroll
                for (int in = 0; in < 4; in++) {
                    const int nb = in >> 1, ns = in & 1;
                    uint32_t b0h = bhr[nb][ns*2], b1h = bhr[nb][ns*2+1];
                    uint32_t b0l = blr[nb][ns*2], b1l = blr[nb][ns*2+1];
                    MMA_BF16(acc[im][in], ahr[im], b0h, b1h);
                    MMA_BF16(acc[im][in], ahr[im], b0l, b1l);
                    MMA_BF16(acc[im][in], alr[im], b0h, b1h);
                }
        }

        if (s + 1 < S) storeS((s + 1) & 1);
        __syncthreads();
    }

    float rp[2][2] = {{0.f, 0.f}, {0.f, 0.f}};   // [im][half] rscore partials

#pragma unroll
    for (int im = 0; im < 2; im++)
#pragma unroll
        for (int in = 0; in < 4; in++) {
            int r = row0 + m0 + im*16 + (lane >> 2);
            int c = col0 + n0 + in*8 + (lane & 3) * 2;
            float bi0 = (c < N)     ? bias[c]     : 0.f;
            float bi1 = (c + 1 < N) ? bias[c + 1] : 0.f;
#pragma unroll
            for (int half = 0; half < 2; half++) {
                int rr = r + half * 8;
                float v0 = acc[im][in][half*2 + 0] + bi0;
                float v1 = acc[im][in][half*2 + 1] + bi1;
                if (EPI == 1) {
                    v0 = fmaxf(v0, 0.f); v1 = fmaxf(v1, 0.f);
                    __nv_bfloat16 h0 = __float2bfloat16(v0);
                    __nv_bfloat16 h1 = __float2bfloat16(v1);
                    __nv_bfloat162 hh; hh.x = h0; hh.y = h1;
                    *(__nv_bfloat162*)&Ch[(size_t)rr*N + c] = hh;
                    __nv_bfloat162 ll;
                    ll.x = __float2bfloat16(v0 - __bfloat162float(h0));
                    ll.y = __float2bfloat16(v1 - __bfloat162float(h1));
                    *(__nv_bfloat162*)&Cl[(size_t)rr*N + c] = ll;
                } else {
                    v0 = 1.f / (1.f + __expf(-v0));
                    v1 = 1.f / (1.f + __expf(-v1));
                    int b = rr / NOUT;
                    if (c < N) {
                        Cf[(size_t)rr*N + c] = v0;
                        float d = xin[(size_t)b*PIX + c] - v0;
                        rp[im][half] += d * d;
                    }
                    if (c + 1 < N) {
                        Cf[(size_t)rr*N + c + 1] = v1;
                        float d = xin[(size_t)b*PIX + c + 1] - v1;
                        rp[im][half] += d * d;
                    }
                }
            }
        }

    if (EPI == 2) {
        // fixed-order reduction: quad shfl -> smem[row][nhalf] -> sum
#pragma unroll
        for (int im = 0; im < 2; im++)
#pragma unroll
            for (int half = 0; half < 2; half++) {
                float s = rp[im][half];
                s += __shfl_xor_sync(0xffffffffu, s, 1);
                s += __shfl_xor_sync(0xffffffffu, s, 2);
                if ((lane & 3) == 0)
                    s_rs[m0 + im*16 + half*8 + (lane >> 2)][warp >> 2] = s;
            }
        __syncthreads();
        if (tid < 128)
            g_rsp[blockIdx.x*BN + row0 + tid] = s_rs[tid][0] + s_rs[tid][1];
    }
}

extern "C" void kernel_launch(void* const* d_in, const int* in_sizes, int n_in,
                              void* d_out, int out_size) {
    const float* incaps = (const float*)d_in[0];
    const float* x      = (const float*)d_in[1];
    const float* weight = (const float*)d_in[2];
    const float* W1     = (const float*)d_in[3];
    const float* b1     = (const float*)d_in[4];
    const float* W2     = (const float*)d_in[5];
    const float* b2     = (const float*)d_in[6];
    const float* W3     = (const float*)d_in[7];
    const float* b3     = (const float*)d_in[8];
    float* out = (float*)d_out;

    cudaFuncSetAttribute(k_gemm_tc<1>, cudaFuncAttributeMaxDynamicSharedMemorySize, GEMM_SMEM);
    cudaFuncSetAttribute(k_gemm_tc<2>, cudaFuncAttributeMaxDynamicSharedMemorySize, GEMM_SMEM);

    __nv_bfloat16 *pW2h, *pW2l, *pW3h, *pW3l, *ph1h, *ph1l, *ph2h, *ph2l;
    float *p_recon;
    cudaGetSymbolAddress((void**)&pW2h, g_W2h);
    cudaGetSymbolAddress((void**)&pW2l, g_W2l);
    cudaGetSymbolAddress((void**)&pW3h, g_W3h);
    cudaGetSymbolAddress((void**)&pW3l, g_W3l);
    cudaGetSymbolAddress((void**)&ph1h, g_h1h);
    cudaGetSymbolAddress((void**)&ph1l, g_h1l);
    cudaGetSymbolAddress((void**)&ph2h, g_h2h);
    cudaGetSymbolAddress((void**)&ph2l, g_h2l);
    cudaGetSymbolAddress((void**)&p_recon, g_recon);

    int tot = BATCH * NOUT * NIN * DOUT;
    k_hat<<<tot/256, 256>>>(incaps, weight);
    k_split2<<<(H1*H2 + H2*PIX + 255)/256, 256>>>(W2, W3);

    for (int it = 0; it < 2; it++) {
        k_routing2<<<BN, RT_THREADS, RT_SMEM>>>(it > 0 ? 1 : 0, 1, nullptr);
        k_scale_c<<<(BATCH*NIN + 255)/256, 256>>>();
        k_h1<<<dim3(BN, 2), 256>>>(W1, b1);
        k_gemm_tc<1><<<dim3(H2/64, BN/128), 256, GEMM_SMEM>>>(
            ph1h, ph1l, pW2h, pW2l, b2, nullptr, ph2h, ph2l, nullptr, H2, H1);
        k_gemm_tc<2><<<dim3(NCB2, BN/128), 256, GEMM_SMEM>>>(
            ph2h, ph2l, pW3h, pW3l, b3, p_recon, nullptr, nullptr, x, PIX, H2);
    }
    k_routing2<<<BN, RT_THREADS, 0>>>(1, 0, out);
}

// round 8
// speedup vs baseline: 3.3714x; 1.1365x over previous
#include <cuda_runtime.h>
#include <cuda_bf16.h>
#include <math.h>
#include <stdint.h>

#define BATCH 128
#define NOUT  10
#define NIN   1152
#define DOUT  16
#define DIN   8
#define H1    512
#define H2    1024
#define PIX   784
#define BN    (BATCH*NOUT)   // 1280
#define NCB2  13             // gemm2 column blocks = ceil(784/64)

// ---- scratch (device globals; no allocations allowed) ----
__device__ float g_hat[(size_t)BATCH*NOUT*NIN*DOUT];  // 94.4 MB
__device__ float g_bcoef[(size_t)BATCH*NOUT*NIN];
__device__ float g_c[(size_t)BATCH*NOUT*NIN];
__device__ float g_outcaps[BN*DOUT];
__device__ float g_recon[(size_t)BN*PIX];
__device__ float g_rsp[NCB2*BN];     // rscore partials [colblk][row]

// hi/lo bf16 split operands
__device__ __nv_bfloat16 g_W2h[(size_t)H1*H2], g_W2l[(size_t)H1*H2];
__device__ __nv_bfloat16 g_W3h[(size_t)H2*PIX], g_W3l[(size_t)H2*PIX];
__device__ __nv_bfloat16 g_h1h[(size_t)BN*H1], g_h1l[(size_t)BN*H1];
__device__ __nv_bfloat16 g_h2h[(size_t)BN*H2], g_h2l[(size_t)BN*H2];

__device__ __forceinline__ uint32_t sptr(const void* p) {
    return (uint32_t)__cvta_generic_to_shared(p);
}

// =======================================================================
// Tiled hat: block = (n, 32 k's, 64 b's). Weight + incaps staged in
// DYNAMIC smem, weight micro-slice register-cached.
// hat[b,n,k,o] = sum_i weight[n,k,o,i] * incaps[b,k,i]
// ws:   [k][132]  (16*8 + 4 pad)         = 4224 floats
// incs: [k][520]  (HB*8 = 512 + 8 pad)   = 16640 floats
// total 20864 floats = 83456 B dynamic smem.
// =======================================================================
#define HB 64
#define HK 32
#define WS_STRIDE   132
#define INCS_STRIDE 520
#define HAT_SMEM ((HK*WS_STRIDE + HK*INCS_STRIDE) * 4)

__global__ void __launch_bounds__(256) k_hat2(
        const float* __restrict__ incaps, const float* __restrict__ weight) {
    extern __shared__ float hsm[];
    float* ws   = hsm;                     // [k][o*8+i] stride WS_STRIDE
    float* incs = hsm + HK*WS_STRIDE;      // [k][b*8+i] stride INCS_STRIDE
    const int n  = blockIdx.z;
    const int kc = blockIdx.x * HK;
    const int bc = blockIdx.y * HB;
    const int tid = threadIdx.x;

    // weight slice: HK*16*8 floats = 1024 float4
    for (int u = tid; u < HK*16*2; u += 256) {
        int k = u >> 5, r = u & 31, o = r >> 1, half = r & 1;
        float4 v = *(const float4*)(weight +
            ((size_t)((n*NIN + kc + k)*16 + o))*8 + half*4);
        *(float4*)&ws[k*WS_STRIDE + o*8 + half*4] = v;
    }
    // incaps slice: HB*HK*8 floats = 4096 float4
    for (int u = tid; u < HB*HK*2; u += 256) {
        int b = u >> 6, r = u & 63, k = r >> 1, half = r & 1;
        float4 v = *(const float4*)(incaps +
            ((size_t)(bc + b)*NIN + kc + k)*8 + half*4);
        *(float4*)&incs[k*INCS_STRIDE + b*8 + half*4] = v;
    }
    __syncthreads();

    const int q   = tid & 3;          // o-quad
    const int k_l = (tid >> 2) & 31;  // k within tile
    const int bh  = tid >> 7;         // b half (0/1)

    float w[4][8];
#pragma unroll
    for (int o2 = 0; o2 < 4; o2++) {
        *(float4*)&w[o2][0] = *(float4*)&ws[k_l*WS_STRIDE + (q*4 + o2)*8];
        *(float4*)&w[o2][4] = *(float4*)&ws[k_l*WS_STRIDE + (q*4 + o2)*8 + 4];
    }

#pragma unroll 4
    for (int bi = 0; bi < 32; bi++) {
        int b = bh*32 + bi;
        float x[8];
        *(float4*)&x[0] = *(float4*)&incs[k_l*INCS_STRIDE + b*8];
        *(float4*)&x[4] = *(float4*)&incs[k_l*INCS_STRIDE + b*8 + 4];
        float4 o4;
        o4.x = w[0][0]*x[0]+w[0][1]*x[1]+w[0][2]*x[2]+w[0][3]*x[3]
             + w[0][4]*x[4]+w[0][5]*x[5]+w[0][6]*x[6]+w[0][7]*x[7];
        o4.y = w[1][0]*x[0]+w[1][1]*x[1]+w[1][2]*x[2]+w[1][3]*x[3]
             + w[1][4]*x[4]+w[1][5]*x[5]+w[1][6]*x[6]+w[1][7]*x[7];
        o4.z = w[2][0]*x[0]+w[2][1]*x[1]+w[2][2]*x[2]+w[2][3]*x[3]
             + w[2][4]*x[4]+w[2][5]*x[5]+w[2][6]*x[6]+w[2][7]*x[7];
        o4.w = w[3][0]*x[0]+w[3][1]*x[1]+w[3][2]*x[2]+w[3][3]*x[3]
             + w[3][4]*x[4]+w[3][5]*x[5]+w[3][6]*x[6]+w[3][7]*x[7];
        *(float4*)(g_hat +
            (((size_t)(bc+b)*NOUT + n)*NIN + kc + k_l)*16 + q*4) = o4;
    }
}

// ---- split W2 and W3 (concatenated) fp32 -> bf16 hi/lo ----
__global__ void k_split2(const float* __restrict__ W2, const float* __restrict__ W3) {
    int i = blockIdx.x * blockDim.x + threadIdx.x;
    const int n2 = H1*H2;
    const int nt = n2 + H2*PIX;
    if (i >= nt) return;
    float v; __nv_bfloat16 *ph, *pl; int j;
    if (i < n2) { v = W2[i]; j = i;       ph = g_W2h; pl = g_W2l; }
    else        { j = i - n2; v = W3[j];  ph = g_W3h; pl = g_W3l; }
    __nv_bfloat16 h = __float2bfloat16(v);
    ph[j] = h;
    pl[j] = __float2bfloat16(v - __bfloat162float(h));
}

// =======================================================================
// Fused routing: one pass over hat. Block = one (b,n), 384 threads.
// Computes r = scale_coef(rscore) inline from g_rsp partials.
// hat tile staged to smem in fp32 (only if do_b) for the bcoef pass.
// =======================================================================
#define RT_THREADS 384
#define RT_SMEM (NIN*DOUT*4)    // 73728 B fp32 staging

__global__ void __launch_bounds__(RT_THREADS) k_routing2(
        int use_rc, int do_b, float* __restrict__ out_vec) {
    extern __shared__ float4 tile4[];        // [NIN*4]
    __shared__ float red[12*16];
    __shared__ float s_oc[16];
    __shared__ float s_rglob;

    const int bn   = blockIdx.x;
    const int tid  = threadIdx.x;
    const int lane = tid & 31, warp = tid >> 5;
    const int q    = tid & 3;                // o-quad
    const int krow = tid >> 2;               // 0..95
    const float* hat = g_hat + (size_t)bn * NIN * DOUT;

    if (use_rc) {
        if (tid == 0) {
            int b = bn / NOUT, n = bn % NOUT;
            float rs[NOUT];
#pragma unroll
            for (int m = 0; m < NOUT; m++) {
                float s = 0.f;
#pragma unroll
                for (int cb = 0; cb < NCB2; cb++) s += g_rsp[cb*BN + b*NOUT + m];
                rs[m] = -s;
            }
            float mn = 1e30f, mx = -1e30f;
#pragma unroll
            for (int m = 0; m < 9; m++) { mn = fminf(mn, rs[m]); mx = fmaxf(mx, rs[m]); }
            float denom = fmaxf(mx - mn, 1e-6f);
            s_rglob = (n == 9) ? 0.5f : fmaxf((rs[n]-mn)/denom, 0.5f);
        }
        __syncthreads();
    }
    const float rglob = use_rc ? s_rglob : 1.0f;

    float rcv[12];
    if (use_rc) {
        const float* cb = g_c + (size_t)bn * NIN;
#pragma unroll
        for (int i = 0; i < 12; i++) rcv[i] = cb[krow + 96*i] * rglob;
    } else {
#pragma unroll
        for (int i = 0; i < 12; i++) rcv[i] = 1.0f;
    }

    float4 v[12];
#pragma unroll
    for (int i = 0; i < 12; i++)
        v[i] = *(const float4*)(hat + ((size_t)(krow + 96*i) * 16) + q * 4);

    float a0 = 0.f, a1 = 0.f, a2 = 0.f, a3 = 0.f;
#pragma unroll
    for (int i = 0; i < 12; i++) {
        if (do_b) tile4[tid + 384*i] = v[i];
        a0 += rcv[i] * v[i].x; a1 += rcv[i] * v[i].y;
        a2 += rcv[i] * v[i].z; a3 += rcv[i] * v[i].w;
    }

#pragma unroll
    for (int m = 4; m <= 16; m <<= 1) {
        a0 += __shfl_xor_sync(0xffffffffu, a0, m);
        a1 += __shfl_xor_sync(0xffffffffu, a1, m);
        a2 += __shfl_xor_sync(0xffffffffu, a2, m);
        a3 += __shfl_xor_sync(0xffffffffu, a3, m);
    }
    if (lane < 4) {
        red[warp*16 + lane*4 + 0] = a0;
        red[warp*16 + lane*4 + 1] = a1;
        red[warp*16 + lane*4 + 2] = a2;
        red[warp*16 + lane*4 + 3] = a3;
    }
    __syncthreads();

    if (tid == 0) {
        float tot[16];
        float n2 = 0.f;
#pragma unroll
        for (int o = 0; o < 16; o++) {
            float s = 0.f;
#pragma unroll
            for (int w = 0; w < 12; w++) s += red[w*16 + o];
            tot[o] = s; n2 += s*s;
        }
        float nrm   = sqrtf(n2);
        float scale = n2 / (1.f + n2) / (nrm + 1e-8f);
        float* dst = out_vec ? out_vec : g_outcaps;
#pragma unroll
        for (int o = 0; o < 16; o++) {
            float vv = scale * tot[o];
            s_oc[o] = vv;
            dst[(size_t)bn*16 + o] = vv;
        }
    }
    __syncthreads();
    if (!do_b) return;

    const float oc0 = s_oc[q*4+0], oc1 = s_oc[q*4+1];
    const float oc2 = s_oc[q*4+2], oc3 = s_oc[q*4+3];
    float* bc = g_bcoef + (size_t)bn * NIN;
#pragma unroll
    for (int i = 0; i < 12; i++) {
        float4 h = tile4[tid + 384*i];
        float p = h.x*oc0 + h.y*oc1 + h.z*oc2 + h.w*oc3;
        p += __shfl_xor_sync(0xffffffffu, p, 1);
        p += __shfl_xor_sync(0xffffffffu, p, 2);
        if (q == 0) bc[krow + 96*i] = p;
    }
}

// =======================================================================
// Fused scale_c + h1 (independent consumers of routing output).
// Blocks [0,576): c = scale_coef(bcoef). Blocks [576, 576+2560): h1.
// =======================================================================
#define SC_BLOCKS ((BATCH*NIN + 255)/256)   // 576
__global__ void __launch_bounds__(256) k_sc_h1(
        const float* __restrict__ W1, const float* __restrict__ b1) {
    if (blockIdx.x < SC_BLOCKS) {
        int idx = blockIdx.x * 256 + threadIdx.x;
        if (idx >= BATCH * NIN) return;
        int b = idx / NIN, k = idx % NIN;
        float v[9];
        float mn = 1e30f, mx = -1e30f;
#pragma unroll
        for (int n = 0; n < 9; n++) {
            float t = g_bcoef[((size_t)b*NOUT + n)*NIN + k];
            v[n] = t; mn = fminf(mn, t); mx = fmaxf(mx, t);
        }
        float denom = fmaxf(mx - mn, 1e-6f);
#pragma unroll
        for (int n = 0; n < 9; n++)
            g_c[((size_t)b*NOUT + n)*NIN + k] = fmaxf((v[n]-mn)/denom, 0.5f);
        g_c[((size_t)b*NOUT + 9)*NIN + k] = 0.5f;
    } else {
        int bid = blockIdx.x - SC_BLOCKS;
        int r = bid >> 1;                         // b*NOUT + m
        int j = (bid & 1) * 256 + threadIdx.x;    // 0..511
        int m = r % NOUT;
        __shared__ float oc[16];
        if (threadIdx.x < 16) oc[threadIdx.x] = g_outcaps[(size_t)r*16 + threadIdx.x];
        __syncthreads();
        float s = b1[j];
#pragma unroll
        for (int d = 0; d < 16; d++)
            s += oc[d] * W1[(size_t)(m*16 + d)*H1 + j];
        float v = fmaxf(s, 0.f);
        __nv_bfloat16 h = __float2bfloat16(v);
        g_h1h[(size_t)r*H1 + j] = h;
        g_h1l[(size_t)r*H1 + j] = __float2bfloat16(v - __bfloat162float(h));
    }
}

// =======================================================================
// Tensor-core GEMM, bf16 hi/lo 3-term compensation (~fp32 precision).
// EPI=1: relu -> Ch/Cl bf16 split.
// EPI=2: sigmoid -> Cf fp32 + fused rscore partials to g_rsp (fixed order).
// =======================================================================
#define MMA_BF16(d, a, b0r, b1r)                                            \
    asm volatile(                                                           \
        "mma.sync.aligned.m16n8k16.row.col.f32.bf16.bf16.f32 "              \
        "{%0,%1,%2,%3},{%4,%5,%6,%7},{%8,%9},{%0,%1,%2,%3};"                \
        : "+f"((d)[0]), "+f"((d)[1]), "+f"((d)[2]), "+f"((d)[3])            \
        : "r"((a)[0]), "r"((a)[1]), "r"((a)[2]), "r"((a)[3]),               \
          "r"(b0r), "r"(b1r))

#define LDSM_X4(r, addr)                                                    \
    asm volatile("ldmatrix.sync.aligned.m8n8.x4.shared.b16 {%0,%1,%2,%3}, [%4];" \
        : "=r"((r)[0]), "=r"((r)[1]), "=r"((r)[2]), "=r"((r)[3]) : "r"(addr))

#define LDSM_X4T(r, addr)                                                   \
    asm volatile("ldmatrix.sync.aligned.m8n8.x4.trans.shared.b16 {%0,%1,%2,%3}, [%4];" \
        : "=r"((r)[0]), "=r"((r)[1]), "=r"((r)[2]), "=r"((r)[3]) : "r"(addr))

#define AS_STRIDE 40   // 32 + 8 pad
#define BS_STRIDE 72   // 64 + 8 pad
#define GEMM_SMEM ((2*2*128*AS_STRIDE + 2*2*32*BS_STRIDE) * 2)

template <int EPI>
__global__ void __launch_bounds__(256) k_gemm_tc(
    const __nv_bfloat16* __restrict__ Ah, const __nv_bfloat16* __restrict__ Al,
    const __nv_bfloat16* __restrict__ Bh, const __nv_bfloat16* __restrict__ Bl,
    const float* __restrict__ bias,
    float* __restrict__ Cf, __nv_bfloat16* __restrict__ Ch,
    __nv_bfloat16* __restrict__ Cl,
    const float* __restrict__ xin,          // EPI==2 only
    int N, int Kd)
{
    extern __shared__ char smem_raw[];
    __nv_bfloat16* As = (__nv_bfloat16*)smem_raw;
    __nv_bfloat16* Bs = As + 2*2*128*AS_STRIDE;
    __shared__ float s_rs[128][2];

    const int tid  = threadIdx.x;
    const int lane = tid & 31, warp = tid >> 5;
    const int row0 = blockIdx.y * 128, col0 = blockIdx.x * 64;
    const int m0 = (warp & 3) * 32, n0 = (warp >> 2) * 32;

    const int arow = tid >> 1, aks = (tid & 1) * 16;
    const int bkr  = tid >> 3, bnc = (tid & 7) * 8;

    float acc[2][4][4];
#pragma unroll
    for (int i = 0; i < 2; i++)
#pragma unroll
        for (int j = 0; j < 4; j++)
#pragma unroll
            for (int q = 0; q < 4; q++) acc[i][j][q] = 0.f;

    const int S = Kd >> 5;
    uint4 pA[4], pB[2];

    const __nv_bfloat16* Abase_h = Ah + (size_t)(row0 + arow) * Kd + aks;
    const __nv_bfloat16* Abase_l = Al + (size_t)(row0 + arow) * Kd + aks;
    const int bcol = col0 + bnc;

    auto loadS = [&](int s) {
        const __nv_bfloat16* pa = Abase_h + s * 32;
        pA[0] = *(const uint4*)pa; pA[1] = *(const uint4*)(pa + 8);
        const __nv_bfloat16* pl = Abase_l + s * 32;
        pA[2] = *(const uint4*)pl; pA[3] = *(const uint4*)(pl + 8);
        const __nv_bfloat16* pbh = Bh + (size_t)(s * 32 + bkr) * N + bcol;
        const __nv_bfloat16* pbl = Bl + (size_t)(s * 32 + bkr) * N + bcol;
        if (bcol + 7 < N) {
            pB[0] = *(const uint4*)pbh; pB[1] = *(const uint4*)pbl;
        } else {
            __nv_bfloat16 th[8], tl[8];
#pragma unroll
            for (int j = 0; j < 8; j++) {
                bool ok = (bcol + j < N);
                th[j] = ok ? pbh[j] : __nv_bfloat16(0.f);
                tl[j] = ok ? pbl[j] : __nv_bfloat16(0.f);
            }
            pB[0] = *(const uint4*)th; pB[1] = *(const uint4*)tl;
        }
    };
    auto storeS = [&](int buf) {
        *(uint4*)&As[((buf*2 + 0)*128 + arow)*AS_STRIDE + aks]     = pA[0];
        *(uint4*)&As[((buf*2 + 0)*128 + arow)*AS_STRIDE + aks + 8] = pA[1];
        *(uint4*)&As[((buf*2 + 1)*128 + arow)*AS_STRIDE + aks]     = pA[2];
        *(uint4*)&As[((buf*2 + 1)*128 + arow)*AS_STRIDE + aks + 8] = pA[3];
        *(uint4*)&Bs[((buf*2 + 0)*32 + bkr)*BS_STRIDE + bnc] = pB[0];
        *(uint4*)&Bs[((buf*2 + 1)*32 + bkr)*BS_STRIDE + bnc] = pB[1];
    };

    const int afr = m0 + (lane & 15);
    const int afc = (lane >> 4) * 8;
    const int bfr = (lane & 15);
    const int bfc = n0 + (lane >> 4) * 8;

    loadS(0); storeS(0);
    __syncthreads();

    for (int s = 0; s < S; s++) {
        const int cur = s & 1;
        if (s + 1 < S) loadS(s + 1);

#pragma unroll
        for (int kf = 0; kf < 2; kf++) {
            uint32_t ahr[2][4], alr[2][4], bhr[2][4], blr[2][4];
#pragma unroll
            for (int im = 0; im < 2; im++) {
                uint32_t ad_h = sptr(&As[((cur*2+0)*128 + afr + im*16)*AS_STRIDE + kf*16 + afc]);
                LDSM_X4(ahr[im], ad_h);
                uint32_t ad_l = sptr(&As[((cur*2+1)*128 + afr + im*16)*AS_STRIDE + kf*16 + afc]);
                LDSM_X4(alr[im], ad_l);
            }
#pragma unroll
            for (int nb = 0; nb < 2; nb++) {
                uint32_t bd_h = sptr(&Bs[((cur*2+0)*32 + kf*16 + bfr)*BS_STRIDE + bfc + nb*16]);
                LDSM_X4T(bhr[nb], bd_h);
                uint32_t bd_l = sptr(&Bs[((cur*2+1)*32 + kf*16 + bfr)*BS_STRIDE + bfc + nb*16]);
                LDSM_X4T(blr[nb], bd_l);
            }
#pragma unroll
            for (int im = 0; im < 2; im++)
#pragma unroll
                for (int in = 0; in < 4; in++) {
                    const int nb = in >> 1, ns = in & 1;
                    uint32_t b0h = bhr[nb][ns*2], b1h = bhr[nb][ns*2+1];
                    uint32_t b0l = blr[nb][ns*2], b1l = blr[nb][ns*2+1];
                    MMA_BF16(acc[im][in], ahr[im], b0h, b1h);
                    MMA_BF16(acc[im][in], ahr[im], b0l, b1l);
                    MMA_BF16(acc[im][in], alr[im], b0h, b1h);
                }
        }

        if (s + 1 < S) storeS((s + 1) & 1);
        __syncthreads();
    }

    float rp[2][2] = {{0.f, 0.f}, {0.f, 0.f}};   // [im][half] rscore partials

#pragma unroll
    for (int im = 0; im < 2; im++)
#pragma unroll
        for (int in = 0; in < 4; in++) {
            int r = row0 + m0 + im*16 + (lane >> 2);
            int c = col0 + n0 + in*8 + (lane & 3) * 2;
            float bi0 = (c < N)     ? bias[c]     : 0.f;
            float bi1 = (c + 1 < N) ? bias[c + 1] : 0.f;
#pragma unroll
            for (int half = 0; half < 2; half++) {
                int rr = r + half * 8;
                float v0 = acc[im][in][half*2 + 0] + bi0;
                float v1 = acc[im][in][half*2 + 1] + bi1;
                if (EPI == 1) {
                    v0 = fmaxf(v0, 0.f); v1 = fmaxf(v1, 0.f);
                    __nv_bfloat16 h0 = __float2bfloat16(v0);
                    __nv_bfloat16 h1 = __float2bfloat16(v1);
                    __nv_bfloat162 hh; hh.x = h0; hh.y = h1;
                    *(__nv_bfloat162*)&Ch[(size_t)rr*N + c] = hh;
                    __nv_bfloat162 ll;
                    ll.x = __float2bfloat16(v0 - __bfloat162float(h0));
                    ll.y = __float2bfloat16(v1 - __bfloat162float(h1));
                    *(__nv_bfloat162*)&Cl[(size_t)rr*N + c] = ll;
                } else {
                    v0 = 1.f / (1.f + __expf(-v0));
                    v1 = 1.f / (1.f + __expf(-v1));
                    int b = rr / NOUT;
                    if (c < N) {
                        Cf[(size_t)rr*N + c] = v0;
                        float d = xin[(size_t)b*PIX + c] - v0;
                        rp[im][half] += d * d;
                    }
                    if (c + 1 < N) {
                        Cf[(size_t)rr*N + c + 1] = v1;
                        float d = xin[(size_t)b*PIX + c + 1] - v1;
                        rp[im][half] += d * d;
                    }
                }
            }
        }

    if (EPI == 2) {
#pragma unroll
        for (int im = 0; im < 2; im++)
#pragma unroll
            for (int half = 0; half < 2; half++) {
                float s = rp[im][half];
                s += __shfl_xor_sync(0xffffffffu, s, 1);
                s += __shfl_xor_sync(0xffffffffu, s, 2);
                if ((lane & 3) == 0)
                    s_rs[m0 + im*16 + half*8 + (lane >> 2)][warp >> 2] = s;
            }
        __syncthreads();
        if (tid < 128)
            g_rsp[blockIdx.x*BN + row0 + tid] = s_rs[tid][0] + s_rs[tid][1];
    }
}

extern "C" void kernel_launch(void* const* d_in, const int* in_sizes, int n_in,
                              void* d_out, int out_size) {
    const float* incaps = (const float*)d_in[0];
    const float* x      = (const float*)d_in[1];
    const float* weight = (const float*)d_in[2];
    const float* W1     = (const float*)d_in[3];
    const float* b1     = (const float*)d_in[4];
    const float* W2     = (const float*)d_in[5];
    const float* b2     = (const float*)d_in[6];
    const float* W3     = (const float*)d_in[7];
    const float* b3     = (const float*)d_in[8];
    float* out = (float*)d_out;

    cudaFuncSetAttribute(k_gemm_tc<1>, cudaFuncAttributeMaxDynamicSharedMemorySize, GEMM_SMEM);
    cudaFuncSetAttribute(k_gemm_tc<2>, cudaFuncAttributeMaxDynamicSharedMemorySize, GEMM_SMEM);
    cudaFuncSetAttribute(k_routing2, cudaFuncAttributeMaxDynamicSharedMemorySize, RT_SMEM);
    cudaFuncSetAttribute(k_hat2, cudaFuncAttributeMaxDynamicSharedMemorySize, HAT_SMEM);

    __nv_bfloat16 *pW2h, *pW2l, *pW3h, *pW3l, *ph1h, *ph1l, *ph2h, *ph2l;
    float *p_recon;
    cudaGetSymbolAddress((void**)&pW2h, g_W2h);
    cudaGetSymbolAddress((void**)&pW2l, g_W2l);
    cudaGetSymbolAddress((void**)&pW3h, g_W3h);
    cudaGetSymbolAddress((void**)&pW3l, g_W3l);
    cudaGetSymbolAddress((void**)&ph1h, g_h1h);
    cudaGetSymbolAddress((void**)&ph1l, g_h1l);
    cudaGetSymbolAddress((void**)&ph2h, g_h2h);
    cudaGetSymbolAddress((void**)&ph2l, g_h2l);
    cudaGetSymbolAddress((void**)&p_recon, g_recon);

    k_hat2<<<dim3(NIN/HK, BATCH/HB, NOUT), 256, HAT_SMEM>>>(incaps, weight);
    k_split2<<<(H1*H2 + H2*PIX + 255)/256, 256>>>(W2, W3);

    for (int it = 0; it < 2; it++) {
        k_routing2<<<BN, RT_THREADS, RT_SMEM>>>(it > 0 ? 1 : 0, 1, nullptr);
        k_sc_h1<<<SC_BLOCKS + 2*BN, 256>>>(W1, b1);
        k_gemm_tc<1><<<dim3(H2/64, BN/128), 256, GEMM_SMEM>>>(
            ph1h, ph1l, pW2h, pW2l, b2, nullptr, ph2h, ph2l, nullptr, H2, H1);
        k_gemm_tc<2><<<dim3(NCB2, BN/128), 256, GEMM_SMEM>>>(
            ph2h, ph2l, pW3h, pW3l, b3, p_recon, nullptr, nullptr, x, PIX, H2);
    }
    k_routing2<<<BN, RT_THREADS, 0>>>(1, 0, out);
}